// round 11
// baseline (speedup 1.0000x reference)
#include <cuda_runtime.h>
#include <cuda_bf16.h>
#include <cstdint>
#include <cstddef>

#define NN 50000
#define DD 256
#define RR 8
#define EE 300000
#define GG 9            // 8 relations + root
#define NB (391 * 8)    // edge buckets: (src block) x relation

// ---------------- device scratch ----------------
__device__ __align__(256) float g_Yroot[(size_t)NN * DD];                 // root-term result
__device__ __align__(256) float g_Yagg[(size_t)NN * DD];                  // relation accumulator
__device__ __align__(256) __nv_bfloat16 g_Ahi[(size_t)NN * DD];
__device__ __align__(256) __nv_bfloat16 g_Alo[(size_t)NN * DD];
__device__ __align__(256) __nv_bfloat16 g_Whi[(size_t)3 * GG * DD * DD];  // [l][g][n][k]
__device__ __align__(256) __nv_bfloat16 g_Wlo[(size_t)3 * GG * DD * DD];
__device__ int g_idx64;
__device__ int g_cnt[NB];
__device__ int g_ofs[NB + 1];
__device__ int g_fill[NB];
__device__ uint32_t g_elist[EE];

// ---------------- edge helpers ----------------
__device__ __forceinline__ bool load_edge(const void* ei, const void* et, int w,
                                          int& src, int& dst, int& rel) {
    long long s, d, r;
    if (g_idx64) {
        s = ((const long long*)ei)[w];
        d = ((const long long*)ei)[EE + w];
        r = ((const long long*)et)[w];
    } else {
        s = ((const int*)ei)[w];
        d = ((const int*)ei)[EE + w];
        r = ((const int*)et)[w];
    }
    if ((unsigned long long)s >= NN || (unsigned long long)d >= NN ||
        (unsigned long long)r >= RR) return false;
    src = (int)s; dst = (int)d; rel = (int)r;
    return true;
}

__global__ void detect_kernel(const int* __restrict__ ei32) {
    int allzero = 1;
    for (int i = 1; i < 64; i += 2)
        if (ei32[i] != 0) allzero = 0;
    g_idx64 = allzero;
}

__global__ void zero_prep_kernel() {      // zero bucket counts + g_Yagg (safety/init)
    int i = blockIdx.x * 256 + threadIdx.x;
    if (i < NB) g_cnt[i] = 0;
    size_t idx = (size_t)blockIdx.x * 256 + threadIdx.x;
    size_t tot = (size_t)NN * DD / 4;
    if (idx < tot) *(float4*)(g_Yagg + idx * 4) = make_float4(0.f, 0.f, 0.f, 0.f);
}

__global__ void count_kernel(const void* __restrict__ ei, const void* __restrict__ et) {
    int w = blockIdx.x * 256 + threadIdx.x;
    if (w >= EE) return;
    int src, dst, rel;
    if (!load_edge(ei, et, w, src, dst, rel)) return;
    atomicAdd(&g_cnt[(src >> 7) * RR + rel], 1);
}

// single-block exclusive scan of g_cnt -> g_ofs / g_fill (1024 thr x 4 buckets)
__global__ void scan_kernel() {
    __shared__ int s[1024];
    int t = threadIdx.x;
    int v[4], sum = 0;
#pragma unroll
    for (int i = 0; i < 4; i++) {
        int b = t * 4 + i;
        v[i] = (b < NB) ? g_cnt[b] : 0;
        sum += v[i];
    }
    s[t] = sum;
    __syncthreads();
    for (int off = 1; off < 1024; off <<= 1) {
        int x = (t >= off) ? s[t - off] : 0;
        __syncthreads();
        s[t] += x;
        __syncthreads();
    }
    int excl = s[t] - sum;
#pragma unroll
    for (int i = 0; i < 4; i++) {
        int b = t * 4 + i;
        if (b < NB) { g_ofs[b] = excl; g_fill[b] = excl; }
        excl += v[i];
    }
    if (t == 1023) g_ofs[NB] = excl;
}

__global__ void fill_kernel(const void* __restrict__ ei, const void* __restrict__ et) {
    int w = blockIdx.x * 256 + threadIdx.x;
    if (w >= EE) return;
    int src, dst, rel;
    if (!load_edge(ei, et, w, src, dst, rel)) return;
    int b = (src >> 7) * RR + rel;
    int pos = atomicAdd(&g_fill[b], 1);
    g_elist[pos] = ((uint32_t)(src & 127) << 17) | (uint32_t)dst;
}

// ---------------- conversion / activation ----------------
__global__ void conv_w_kernel(const float* __restrict__ weights, const float* __restrict__ roots) {
    size_t i = (size_t)blockIdx.x * 256 + threadIdx.x;
    if (i >= (size_t)3 * GG * DD * DD) return;
    int k = (int)(i & 255);
    int n = (int)((i >> 8) & 255);
    int lg = (int)(i >> 16);
    int l = lg / GG, g = lg % GG;
    float w = (g < 8) ? weights[(((size_t)(l * 8 + g)) * DD + k) * DD + n]
                      : roots[((size_t)l * DD + k) * DD + n];
    __nv_bfloat16 hi = __float2bfloat16(w);
    g_Whi[i] = hi;
    g_Wlo[i] = __float2bfloat16(w - __bfloat162float(hi));
}

__global__ void conv_x_kernel(const float* __restrict__ x) {
    int i = blockIdx.x * 256 + threadIdx.x;
    if (i >= NN * DD) return;
    float a = x[i];
    __nv_bfloat16 hi = __float2bfloat16(a);
    g_Ahi[i] = hi;
    g_Alo[i] = __float2bfloat16(a - __bfloat162float(hi));
}

// relu(root+agg) -> split bf16 hi/lo; re-zero agg for next layer.
__global__ void act_split_kernel() {
    int i = blockIdx.x * 256 + threadIdx.x;
    if (i >= NN * DD) return;
    float v = fmaxf(g_Yroot[i] + g_Yagg[i], 0.f);
    g_Yagg[i] = 0.f;
    __nv_bfloat16 hi = __float2bfloat16(v);
    g_Ahi[i] = hi;
    g_Alo[i] = __float2bfloat16(v - __bfloat162float(hi));
}

// sigmoid(root+agg) -> out; re-zero agg for next graph replay.
__global__ void act_final_kernel(float* __restrict__ out) {
    int i = blockIdx.x * 256 + threadIdx.x;
    if (i >= NN * DD) return;
    float v = g_Yroot[i] + g_Yagg[i];
    g_Yagg[i] = 0.f;
    out[i] = 1.f / (1.f + expf(-v));
}

// ---------------- HMMA GEMM + fused scatter epilogue ----------------
#define BM 128
#define BN 128
#define BK 32
#define STAGES 3
#define LDS_B 64
#define ARR (128 * LDS_B)
#define OFF_AHI 0
#define OFF_ALO ARR
#define OFF_BHI (2 * ARR)
#define OFF_BLO (3 * ARR)
#define STAGE_BYTES (4 * ARR)              // 32768
#define SMEM_TOTAL (STAGES * STAGE_BYTES)  // 98304 -> 2 CTAs/SM
#define CS_STRIDE 132                      // fp32 C staging row stride (padded)

#define CP_ASYNC16(dst, src, srcsz) \
    asm volatile("cp.async.cg.shared.global [%0], [%1], 16, %2;" \
                 :: "r"(dst), "l"(src), "r"(srcsz) : "memory")
#define CP_COMMIT() asm volatile("cp.async.commit_group;" ::: "memory")
#define CP_WAIT1()  asm volatile("cp.async.wait_group 1;" ::: "memory")

#define LDMX4(r, a) \
    asm volatile("ldmatrix.sync.aligned.m8n8.x4.shared.b16 {%0,%1,%2,%3}, [%4];" \
        : "=r"((r)[0]), "=r"((r)[1]), "=r"((r)[2]), "=r"((r)[3]) : "r"(a))

__device__ __forceinline__ uint32_t smem_u32(const void* p) {
    uint32_t a;
    asm("{ .reg .u64 t; cvta.to.shared.u64 t, %1; cvt.u32.u64 %0, t; }" : "=r"(a) : "l"(p));
    return a;
}
__device__ __forceinline__ uint32_t swz(uint32_t row, uint32_t j) {
    return row * LDS_B + ((j ^ ((row >> 1) & 3u)) << 4);
}
__device__ __forceinline__ void mma16816(float* d, const uint32_t* a, const uint32_t* b) {
    asm volatile(
        "mma.sync.aligned.m16n8k16.row.col.f32.bf16.bf16.f32 "
        "{%0,%1,%2,%3}, {%4,%5,%6,%7}, {%8,%9}, {%0,%1,%2,%3};"
        : "+f"(d[0]), "+f"(d[1]), "+f"(d[2]), "+f"(d[3])
        : "r"(a[0]), "r"(a[1]), "r"(a[2]), "r"(a[3]), "r"(b[0]), "r"(b[1]));
}

// Single launch, 18 n-tiles: group<8 relation (atomic into g_Yagg), group==8 root.
__global__ __launch_bounds__(256, 2)
void gemm_kernel(const float* __restrict__ bias, int lay) {
    extern __shared__ char smem[];
    const uint32_t sb = smem_u32(smem);
    const int t = threadIdx.x;
    const int wid = t >> 5, lane = t & 31;
    const int g = lane >> 2, t4 = lane & 3;
    const int m0 = blockIdx.x * BM;
    const int nt = blockIdx.y;
    const int warp_m = wid & 3, warp_n = wid >> 2;   // 4 x 2 warp grid

    const int group = nt >> 1, nh = nt & 1;          // group 0..7 rel, 8 root
    const __nv_bfloat16* Bh = g_Whi + ((size_t)(lay * GG + group) * DD + nh * 128) * DD;
    const __nv_bfloat16* Bl = g_Wlo + ((size_t)(lay * GG + group) * DD + nh * 128) * DD;

    float acc[2][8][4];
#pragma unroll
    for (int mi = 0; mi < 2; mi++)
#pragma unroll
        for (int nj = 0; nj < 8; nj++)
#pragma unroll
            for (int q = 0; q < 4; q++) acc[mi][nj][q] = 0.f;

    const int lr = lane & 7;
    const int l8 = (lane >> 3) & 1;
    const int l16 = (lane >> 4) & 1;

    auto load_stage = [&](int kt, int stage) {
        const int k0 = kt * BK;
        const uint32_t stb = sb + stage * STAGE_BYTES;
#pragma unroll
        for (int i = 0; i < 2; i++) {
            int c = t + i * 256;
            uint32_t row = (uint32_t)(c >> 2);
            uint32_t j = (uint32_t)(c & 3);
            uint32_t doff = swz(row, j);
            int col8 = (int)j * 8;
            int gr = m0 + (int)row;
            uint32_t asz = (gr < NN) ? 16u : 0u;
            int grc = (gr < NN) ? gr : 0;
            CP_ASYNC16(stb + OFF_AHI + doff, g_Ahi + (size_t)grc * DD + k0 + col8, asz);
            CP_ASYNC16(stb + OFF_ALO + doff, g_Alo + (size_t)grc * DD + k0 + col8, asz);
            CP_ASYNC16(stb + OFF_BHI + doff, Bh + (size_t)row * DD + k0 + col8, 16u);
            CP_ASYNC16(stb + OFF_BLO + doff, Bl + (size_t)row * DD + k0 + col8, 16u);
        }
    };

    load_stage(0, 0);
    CP_COMMIT();
    load_stage(1, 1);
    CP_COMMIT();

    const int NKT = DD / BK;   // 8
#pragma unroll
    for (int kt = 0; kt < NKT; kt++) {
        CP_WAIT1();
        __syncthreads();
        if (kt + 2 < NKT) load_stage(kt + 2, (kt + 2) % STAGES);
        CP_COMMIT();

        const uint32_t stf = sb + (kt % STAGES) * STAGE_BYTES;
#pragma unroll
        for (int h = 0; h < 2; h++) {
            uint32_t ahi[2][4], alo[2][4], bhi[4][4], blo[4][4];
            {
                uint32_t jA = (uint32_t)(h * 2 + l16);
#pragma unroll
                for (int mi = 0; mi < 2; mi++) {
                    uint32_t arow = (uint32_t)(warp_m * 32 + mi * 16 + l8 * 8 + lr);
                    uint32_t ao = stf + swz(arow, jA);
                    LDMX4(ahi[mi], ao + OFF_AHI);
                    LDMX4(alo[mi], ao + OFF_ALO);
                }
            }
            {
                uint32_t jB = (uint32_t)(h * 2 + l8);
#pragma unroll
                for (int p = 0; p < 4; p++) {
                    uint32_t brow = (uint32_t)(warp_n * 64 + p * 16 + l16 * 8 + lr);
                    uint32_t bo = stf + swz(brow, jB);
                    LDMX4(bhi[p], bo + OFF_BHI);
                    LDMX4(blo[p], bo + OFF_BLO);
                }
            }
#pragma unroll
            for (int term = 0; term < 3; term++) {
#pragma unroll
                for (int mi = 0; mi < 2; mi++)
#pragma unroll
                    for (int p = 0; p < 4; p++) {
                        const uint32_t* af = (term == 2) ? alo[mi] : ahi[mi];
                        const uint32_t* bf = (term == 1) ? blo[p] : bhi[p];
                        mma16816(acc[mi][2 * p],     af, &bf[0]);
                        mma16816(acc[mi][2 * p + 1], af, &bf[2]);
                    }
            }
        }
    }

    if (group == 8) {
        // Root epilogue: plain store + bias -> g_Yroot.
#pragma unroll
        for (int mi = 0; mi < 2; mi++) {
            int row0 = m0 + warp_m * 32 + mi * 16 + g;
#pragma unroll
            for (int nj = 0; nj < 8; nj++) {
                int c = nh * 128 + warp_n * 64 + nj * 8 + t4 * 2;
                float b0 = bias[c], b1 = bias[c + 1];
                if (row0 < NN)
                    *(float2*)(g_Yroot + (size_t)row0 * DD + c) =
                        make_float2(acc[mi][nj][0] + b0, acc[mi][nj][1] + b1);
                if (row0 + 8 < NN)
                    *(float2*)(g_Yroot + (size_t)(row0 + 8) * DD + c) =
                        make_float2(acc[mi][nj][2] + b0, acc[mi][nj][3] + b1);
            }
        }
    } else {
        // Fused scatter epilogue: stage C in smem, walk this (block, rel) bucket.
        __syncthreads();                       // all stage-buffer reads done
        float* cs = (float*)smem;              // [128][CS_STRIDE]
#pragma unroll
        for (int mi = 0; mi < 2; mi++) {
            int r0 = warp_m * 32 + mi * 16 + g;
#pragma unroll
            for (int nj = 0; nj < 8; nj++) {
                int cl = warp_n * 64 + nj * 8 + t4 * 2;
                *(float2*)(cs + r0 * CS_STRIDE + cl) =
                    make_float2(acc[mi][nj][0], acc[mi][nj][1]);
                *(float2*)(cs + (r0 + 8) * CS_STRIDE + cl) =
                    make_float2(acc[mi][nj][2], acc[mi][nj][3]);
            }
        }
        __syncthreads();
        const int bid = blockIdx.x * RR + group;
        const int beg = g_ofs[bid], end = g_ofs[bid + 1];
        for (int i = beg + wid; i < end; i += 8) {
            uint32_t e = g_elist[i];
            int sl = (int)(e >> 17);
            int dst = (int)(e & 0x1FFFF);
            float4 v = *(const float4*)(cs + sl * CS_STRIDE + lane * 4);
            float* p = g_Yagg + (size_t)dst * DD + nh * 128 + lane * 4;
            asm volatile("red.global.add.v4.f32 [%0], {%1, %2, %3, %4};"
                         :: "l"(p), "f"(v.x), "f"(v.y), "f"(v.z), "f"(v.w) : "memory");
        }
    }
}

// ---------------- launch ----------------
extern "C" void kernel_launch(void* const* d_in, const int* in_sizes, int n_in,
                              void* d_out, int out_size) {
    const float* x       = (const float*)d_in[0];
    const float* weights = (const float*)d_in[1];
    const float* roots   = (const float*)d_in[2];
    const float* biases  = (const float*)d_in[3];
    const void*  ei      = d_in[4];
    const void*  et      = d_in[5];

    cudaFuncSetAttribute(gemm_kernel, cudaFuncAttributeMaxDynamicSharedMemorySize, SMEM_TOTAL);

    detect_kernel<<<1, 1>>>((const int*)ei);
    zero_prep_kernel<<<(NN * DD / 4 + 255) / 256, 256>>>();
    conv_w_kernel<<<(3 * GG * DD * DD + 255) / 256, 256>>>(weights, roots);
    conv_x_kernel<<<(NN * DD + 255) / 256, 256>>>(x);
    count_kernel<<<(EE + 255) / 256, 256>>>(ei, et);
    scan_kernel<<<1, 1024>>>();
    fill_kernel<<<(EE + 255) / 256, 256>>>(ei, et);

    for (int l = 0; l < 3; l++) {
        gemm_kernel<<<dim3(391, 18), 256, SMEM_TOTAL>>>(biases + (size_t)l * DD, l);
        if (l < 2)
            act_split_kernel<<<(NN * DD + 255) / 256, 256>>>();
        else
            act_final_kernel<<<(NN * DD + 255) / 256, 256>>>((float*)d_out);
    }
}

// round 12
// speedup vs baseline: 1.4015x; 1.4015x over previous
#include <cuda_runtime.h>
#include <cuda_bf16.h>
#include <cstdint>
#include <cstddef>

#define NN 50000
#define DD 256
#define RR 8
#define EE 300000
#define GG 9            // 8 relations + root
#define NB (391 * 8)    // edge buckets: (src block) x relation

// ---------------- device scratch ----------------
__device__ __align__(256) float g_Yroot[(size_t)NN * DD];                 // root-term result
__device__ __align__(256) float g_Yagg[(size_t)NN * DD];                  // relation accumulator
__device__ __align__(256) __nv_bfloat16 g_Ahi[(size_t)NN * DD];
__device__ __align__(256) __nv_bfloat16 g_Alo[(size_t)NN * DD];
__device__ __align__(256) __nv_bfloat16 g_Whi[(size_t)3 * GG * DD * DD];  // [l][g][n][k]
__device__ __align__(256) __nv_bfloat16 g_Wlo[(size_t)3 * GG * DD * DD];
__device__ int g_idx64;
__device__ int g_cnt[NB];
__device__ int g_ofs[NB + 1];
__device__ int g_fill[NB];
__device__ uint32_t g_elist[EE];

// ---------------- edge helpers ----------------
__device__ __forceinline__ bool load_edge(const void* ei, const void* et, int w,
                                          int& src, int& dst, int& rel) {
    long long s, d, r;
    if (g_idx64) {
        s = ((const long long*)ei)[w];
        d = ((const long long*)ei)[EE + w];
        r = ((const long long*)et)[w];
    } else {
        s = ((const int*)ei)[w];
        d = ((const int*)ei)[EE + w];
        r = ((const int*)et)[w];
    }
    if ((unsigned long long)s >= NN || (unsigned long long)d >= NN ||
        (unsigned long long)r >= RR) return false;
    src = (int)s; dst = (int)d; rel = (int)r;
    return true;
}

__global__ void detect_kernel(const int* __restrict__ ei32) {
    int allzero = 1;
    for (int i = 1; i < 64; i += 2)
        if (ei32[i] != 0) allzero = 0;
    g_idx64 = allzero;
}

__global__ void zero_prep_kernel() {      // zero bucket counts + g_Yagg (init)
    int i = blockIdx.x * 256 + threadIdx.x;
    if (i < NB) g_cnt[i] = 0;
    size_t idx = (size_t)blockIdx.x * 256 + threadIdx.x;
    size_t tot = (size_t)NN * DD / 4;
    if (idx < tot) *(float4*)(g_Yagg + idx * 4) = make_float4(0.f, 0.f, 0.f, 0.f);
}

__global__ void count_kernel(const void* __restrict__ ei, const void* __restrict__ et) {
    int w = blockIdx.x * 256 + threadIdx.x;
    if (w >= EE) return;
    int src, dst, rel;
    if (!load_edge(ei, et, w, src, dst, rel)) return;
    atomicAdd(&g_cnt[(src >> 7) * RR + rel], 1);
}

// single-block exclusive scan of g_cnt -> g_ofs / g_fill (1024 thr x 4 buckets)
__global__ void scan_kernel() {
    __shared__ int s[1024];
    int t = threadIdx.x;
    int v[4], sum = 0;
#pragma unroll
    for (int i = 0; i < 4; i++) {
        int b = t * 4 + i;
        v[i] = (b < NB) ? g_cnt[b] : 0;
        sum += v[i];
    }
    s[t] = sum;
    __syncthreads();
    for (int off = 1; off < 1024; off <<= 1) {
        int x = (t >= off) ? s[t - off] : 0;
        __syncthreads();
        s[t] += x;
        __syncthreads();
    }
    int excl = s[t] - sum;
#pragma unroll
    for (int i = 0; i < 4; i++) {
        int b = t * 4 + i;
        if (b < NB) { g_ofs[b] = excl; g_fill[b] = excl; }
        excl += v[i];
    }
    if (t == 1023) g_ofs[NB] = excl;
}

__global__ void fill_kernel(const void* __restrict__ ei, const void* __restrict__ et) {
    int w = blockIdx.x * 256 + threadIdx.x;
    if (w >= EE) return;
    int src, dst, rel;
    if (!load_edge(ei, et, w, src, dst, rel)) return;
    int b = (src >> 7) * RR + rel;
    int pos = atomicAdd(&g_fill[b], 1);
    g_elist[pos] = ((uint32_t)(src & 127) << 17) | (uint32_t)dst;
}

// ---------------- conversion / activation ----------------
__global__ void conv_w_kernel(const float* __restrict__ weights, const float* __restrict__ roots) {
    size_t i = (size_t)blockIdx.x * 256 + threadIdx.x;
    if (i >= (size_t)3 * GG * DD * DD) return;
    int k = (int)(i & 255);
    int n = (int)((i >> 8) & 255);
    int lg = (int)(i >> 16);
    int l = lg / GG, g = lg % GG;
    float w = (g < 8) ? weights[(((size_t)(l * 8 + g)) * DD + k) * DD + n]
                      : roots[((size_t)l * DD + k) * DD + n];
    __nv_bfloat16 hi = __float2bfloat16(w);
    g_Whi[i] = hi;
    g_Wlo[i] = __float2bfloat16(w - __bfloat162float(hi));
}

__global__ void conv_x_kernel(const float* __restrict__ x) {
    int i = blockIdx.x * 256 + threadIdx.x;
    if (i >= NN * DD) return;
    float a = x[i];
    __nv_bfloat16 hi = __float2bfloat16(a);
    g_Ahi[i] = hi;
    g_Alo[i] = __float2bfloat16(a - __bfloat162float(hi));
}

// relu(root+agg) -> split bf16 hi/lo; re-zero agg for next layer. float4-vectorized.
__global__ void act_split_kernel() {
    int q = blockIdx.x * 256 + threadIdx.x;         // over NN*DD/4
    if (q >= NN * (DD / 4)) return;
    float4 r = *(const float4*)(g_Yroot + (size_t)q * 4);
    float4 a = *(const float4*)(g_Yagg + (size_t)q * 4);
    *(float4*)(g_Yagg + (size_t)q * 4) = make_float4(0.f, 0.f, 0.f, 0.f);
    float v[4] = { fmaxf(r.x + a.x, 0.f), fmaxf(r.y + a.y, 0.f),
                   fmaxf(r.z + a.z, 0.f), fmaxf(r.w + a.w, 0.f) };
    __nv_bfloat16 hi[4], lo[4];
#pragma unroll
    for (int i = 0; i < 4; i++) {
        hi[i] = __float2bfloat16(v[i]);
        lo[i] = __float2bfloat16(v[i] - __bfloat162float(hi[i]));
    }
    *(uint2*)(g_Ahi + (size_t)q * 4) = *(uint2*)hi;
    *(uint2*)(g_Alo + (size_t)q * 4) = *(uint2*)lo;
}

// sigmoid(root+agg) -> out; re-zero agg for graph-replay determinism.
__global__ void act_final_kernel(float* __restrict__ out) {
    int q = blockIdx.x * 256 + threadIdx.x;         // over NN*DD/4
    if (q >= NN * (DD / 4)) return;
    float4 r = *(const float4*)(g_Yroot + (size_t)q * 4);
    float4 a = *(const float4*)(g_Yagg + (size_t)q * 4);
    *(float4*)(g_Yagg + (size_t)q * 4) = make_float4(0.f, 0.f, 0.f, 0.f);
    float4 o;
    o.x = 1.f / (1.f + expf(-(r.x + a.x)));
    o.y = 1.f / (1.f + expf(-(r.y + a.y)));
    o.z = 1.f / (1.f + expf(-(r.z + a.z)));
    o.w = 1.f / (1.f + expf(-(r.w + a.w)));
    *(float4*)(out + (size_t)q * 4) = o;
}

// ---------------- HMMA GEMM + fused scatter epilogue ----------------
#define BM 128
#define BN 128
#define BK 32
#define STAGES 3
#define LDS_B 64
#define ARR (128 * LDS_B)
#define OFF_AHI 0
#define OFF_ALO ARR
#define OFF_BHI (2 * ARR)
#define OFF_BLO (3 * ARR)
#define STAGE_BYTES (4 * ARR)              // 32768
#define SMEM_TOTAL (STAGES * STAGE_BYTES)  // 98304 -> 2 CTAs/SM
#define CS_STRIDE 132                      // fp32 C staging row stride (padded)

#define CP_ASYNC16(dst, src, srcsz) \
    asm volatile("cp.async.cg.shared.global [%0], [%1], 16, %2;" \
                 :: "r"(dst), "l"(src), "r"(srcsz) : "memory")
#define CP_COMMIT() asm volatile("cp.async.commit_group;" ::: "memory")
#define CP_WAIT1()  asm volatile("cp.async.wait_group 1;" ::: "memory")

#define LDMX4(r, a) \
    asm volatile("ldmatrix.sync.aligned.m8n8.x4.shared.b16 {%0,%1,%2,%3}, [%4];" \
        : "=r"((r)[0]), "=r"((r)[1]), "=r"((r)[2]), "=r"((r)[3]) : "r"(a))

__device__ __forceinline__ uint32_t smem_u32(const void* p) {
    uint32_t a;
    asm("{ .reg .u64 t; cvta.to.shared.u64 t, %1; cvt.u32.u64 %0, t; }" : "=r"(a) : "l"(p));
    return a;
}
__device__ __forceinline__ uint32_t swz(uint32_t row, uint32_t j) {
    return row * LDS_B + ((j ^ ((row >> 1) & 3u)) << 4);
}
__device__ __forceinline__ void mma16816(float* d, const uint32_t* a, const uint32_t* b) {
    asm volatile(
        "mma.sync.aligned.m16n8k16.row.col.f32.bf16.bf16.f32 "
        "{%0,%1,%2,%3}, {%4,%5,%6,%7}, {%8,%9}, {%0,%1,%2,%3};"
        : "+f"(d[0]), "+f"(d[1]), "+f"(d[2]), "+f"(d[3])
        : "r"(a[0]), "r"(a[1]), "r"(a[2]), "r"(a[3]), "r"(b[0]), "r"(b[1]));
}

// Single launch, 18 n-tiles: group<8 relation (atomic into g_Yagg), group==8 root.
__global__ __launch_bounds__(256, 2)
void gemm_kernel(const float* __restrict__ bias, int lay) {
    extern __shared__ char smem[];
    const uint32_t sb = smem_u32(smem);
    const int t = threadIdx.x;
    const int wid = t >> 5, lane = t & 31;
    const int g = lane >> 2, t4 = lane & 3;
    const int m0 = blockIdx.x * BM;
    const int nt = blockIdx.y;
    const int warp_m = wid & 3, warp_n = wid >> 2;   // 4 x 2 warp grid

    const int group = nt >> 1, nh = nt & 1;          // group 0..7 rel, 8 root
    const __nv_bfloat16* Bh = g_Whi + ((size_t)(lay * GG + group) * DD + nh * 128) * DD;
    const __nv_bfloat16* Bl = g_Wlo + ((size_t)(lay * GG + group) * DD + nh * 128) * DD;

    float acc[2][8][4];
#pragma unroll
    for (int mi = 0; mi < 2; mi++)
#pragma unroll
        for (int nj = 0; nj < 8; nj++)
#pragma unroll
            for (int q = 0; q < 4; q++) acc[mi][nj][q] = 0.f;

    const int lr = lane & 7;
    const int l8 = (lane >> 3) & 1;
    const int l16 = (lane >> 4) & 1;

    auto load_stage = [&](int kt, int stage) {
        const int k0 = kt * BK;
        const uint32_t stb = sb + stage * STAGE_BYTES;
#pragma unroll
        for (int i = 0; i < 2; i++) {
            int c = t + i * 256;
            uint32_t row = (uint32_t)(c >> 2);
            uint32_t j = (uint32_t)(c & 3);
            uint32_t doff = swz(row, j);
            int col8 = (int)j * 8;
            int gr = m0 + (int)row;
            uint32_t asz = (gr < NN) ? 16u : 0u;
            int grc = (gr < NN) ? gr : 0;
            CP_ASYNC16(stb + OFF_AHI + doff, g_Ahi + (size_t)grc * DD + k0 + col8, asz);
            CP_ASYNC16(stb + OFF_ALO + doff, g_Alo + (size_t)grc * DD + k0 + col8, asz);
            CP_ASYNC16(stb + OFF_BHI + doff, Bh + (size_t)row * DD + k0 + col8, 16u);
            CP_ASYNC16(stb + OFF_BLO + doff, Bl + (size_t)row * DD + k0 + col8, 16u);
        }
    };

    load_stage(0, 0);
    CP_COMMIT();
    load_stage(1, 1);
    CP_COMMIT();

    const int NKT = DD / BK;   // 8  (NOT unrolled: keeps regs at 128, no spills)
    for (int kt = 0; kt < NKT; kt++) {
        CP_WAIT1();
        __syncthreads();
        if (kt + 2 < NKT) load_stage(kt + 2, (kt + 2) % STAGES);
        CP_COMMIT();

        const uint32_t stf = sb + (kt % STAGES) * STAGE_BYTES;
#pragma unroll
        for (int h = 0; h < 2; h++) {
            uint32_t ahi[2][4], alo[2][4], bhi[4][4], blo[4][4];
            {
                uint32_t jA = (uint32_t)(h * 2 + l16);
#pragma unroll
                for (int mi = 0; mi < 2; mi++) {
                    uint32_t arow = (uint32_t)(warp_m * 32 + mi * 16 + l8 * 8 + lr);
                    uint32_t ao = stf + swz(arow, jA);
                    LDMX4(ahi[mi], ao + OFF_AHI);
                    LDMX4(alo[mi], ao + OFF_ALO);
                }
            }
            {
                uint32_t jB = (uint32_t)(h * 2 + l8);
#pragma unroll
                for (int p = 0; p < 4; p++) {
                    uint32_t brow = (uint32_t)(warp_n * 64 + p * 16 + l16 * 8 + lr);
                    uint32_t bo = stf + swz(brow, jB);
                    LDMX4(bhi[p], bo + OFF_BHI);
                    LDMX4(blo[p], bo + OFF_BLO);
                }
            }
#pragma unroll
            for (int term = 0; term < 3; term++) {
#pragma unroll
                for (int mi = 0; mi < 2; mi++)
#pragma unroll
                    for (int p = 0; p < 4; p++) {
                        const uint32_t* af = (term == 2) ? alo[mi] : ahi[mi];
                        const uint32_t* bf = (term == 1) ? blo[p] : bhi[p];
                        mma16816(acc[mi][2 * p],     af, &bf[0]);
                        mma16816(acc[mi][2 * p + 1], af, &bf[2]);
                    }
            }
        }
    }

    if (group == 8) {
        // Root epilogue: plain store + bias -> g_Yroot.
#pragma unroll
        for (int mi = 0; mi < 2; mi++) {
            int row0 = m0 + warp_m * 32 + mi * 16 + g;
#pragma unroll
            for (int nj = 0; nj < 8; nj++) {
                int c = nh * 128 + warp_n * 64 + nj * 8 + t4 * 2;
                float b0 = bias[c], b1 = bias[c + 1];
                if (row0 < NN)
                    *(float2*)(g_Yroot + (size_t)row0 * DD + c) =
                        make_float2(acc[mi][nj][0] + b0, acc[mi][nj][1] + b1);
                if (row0 + 8 < NN)
                    *(float2*)(g_Yroot + (size_t)(row0 + 8) * DD + c) =
                        make_float2(acc[mi][nj][2] + b0, acc[mi][nj][3] + b1);
            }
        }
    } else {
        // Fused scatter epilogue: stage C in smem, walk this (block, rel) bucket.
        __syncthreads();                       // all stage-buffer reads done
        float* cs = (float*)smem;              // [128][CS_STRIDE]
#pragma unroll
        for (int mi = 0; mi < 2; mi++) {
            int r0 = warp_m * 32 + mi * 16 + g;
#pragma unroll
            for (int nj = 0; nj < 8; nj++) {
                int cl = warp_n * 64 + nj * 8 + t4 * 2;
                *(float2*)(cs + r0 * CS_STRIDE + cl) =
                    make_float2(acc[mi][nj][0], acc[mi][nj][1]);
                *(float2*)(cs + (r0 + 8) * CS_STRIDE + cl) =
                    make_float2(acc[mi][nj][2], acc[mi][nj][3]);
            }
        }
        __syncthreads();
        const int bid = blockIdx.x * RR + group;
        const int beg = g_ofs[bid], end = g_ofs[bid + 1];
        for (int i = beg + wid; i < end; i += 8) {
            uint32_t e = g_elist[i];
            int sl = (int)(e >> 17);
            int dst = (int)(e & 0x1FFFF);
            float4 v = *(const float4*)(cs + sl * CS_STRIDE + lane * 4);
            float* p = g_Yagg + (size_t)dst * DD + nh * 128 + lane * 4;
            asm volatile("red.global.add.v4.f32 [%0], {%1, %2, %3, %4};"
                         :: "l"(p), "f"(v.x), "f"(v.y), "f"(v.z), "f"(v.w) : "memory");
        }
    }
}

// ---------------- launch ----------------
extern "C" void kernel_launch(void* const* d_in, const int* in_sizes, int n_in,
                              void* d_out, int out_size) {
    const float* x       = (const float*)d_in[0];
    const float* weights = (const float*)d_in[1];
    const float* roots   = (const float*)d_in[2];
    const float* biases  = (const float*)d_in[3];
    const void*  ei      = d_in[4];
    const void*  et      = d_in[5];

    cudaFuncSetAttribute(gemm_kernel, cudaFuncAttributeMaxDynamicSharedMemorySize, SMEM_TOTAL);

    detect_kernel<<<1, 1>>>((const int*)ei);
    zero_prep_kernel<<<(NN * DD / 4 + 255) / 256, 256>>>();
    conv_w_kernel<<<(3 * GG * DD * DD + 255) / 256, 256>>>(weights, roots);
    conv_x_kernel<<<(NN * DD + 255) / 256, 256>>>(x);
    count_kernel<<<(EE + 255) / 256, 256>>>(ei, et);
    scan_kernel<<<1, 1024>>>();
    fill_kernel<<<(EE + 255) / 256, 256>>>(ei, et);

    for (int l = 0; l < 3; l++) {
        gemm_kernel<<<dim3(391, 18), 256, SMEM_TOTAL>>>(biases + (size_t)l * DD, l);
        if (l < 2)
            act_split_kernel<<<(NN * DD / 4 + 255) / 256, 256>>>();
        else
            act_final_kernel<<<(NN * DD / 4 + 255) / 256, 256>>>((float*)d_out);
    }
}

// round 13
// speedup vs baseline: 1.7267x; 1.2321x over previous
#include <cuda_runtime.h>
#include <cuda_bf16.h>
#include <cstdint>
#include <cstddef>

#define NN 50000
#define DD 256
#define RR 8
#define EE 300000
#define GG 9            // 8 relations + root
#define NB (391 * 8)    // edge buckets: (src block) x relation

// ---------------- device scratch ----------------
__device__ __align__(256) float g_Yroot[(size_t)NN * DD];                 // single accumulator
__device__ __align__(256) __nv_bfloat16 g_Ahi[(size_t)NN * DD];
__device__ __align__(256) __nv_bfloat16 g_Alo[(size_t)NN * DD];
__device__ __align__(256) __nv_bfloat16 g_Whi[(size_t)3 * GG * DD * DD];  // [l][g][n][k]
__device__ __align__(256) __nv_bfloat16 g_Wlo[(size_t)3 * GG * DD * DD];
__device__ int g_idx64;
__device__ int g_cnt[NB];
__device__ int g_ofs[NB + 1];
__device__ int g_fill[NB];
__device__ uint32_t g_elist[EE];

// ---------------- edge helpers ----------------
__device__ __forceinline__ bool load_edge(const void* ei, const void* et, int w,
                                          int& src, int& dst, int& rel) {
    long long s, d, r;
    if (g_idx64) {
        s = ((const long long*)ei)[w];
        d = ((const long long*)ei)[EE + w];
        r = ((const long long*)et)[w];
    } else {
        s = ((const int*)ei)[w];
        d = ((const int*)ei)[EE + w];
        r = ((const int*)et)[w];
    }
    if ((unsigned long long)s >= NN || (unsigned long long)d >= NN ||
        (unsigned long long)r >= RR) return false;
    src = (int)s; dst = (int)d; rel = (int)r;
    return true;
}

__global__ void detect_kernel(const int* __restrict__ ei32) {
    int allzero = 1;
    for (int i = 1; i < 64; i += 2)
        if (ei32[i] != 0) allzero = 0;
    g_idx64 = allzero;
}

// Init g_Yroot with layer-0 bias (runs every graph replay) + zero bucket counts.
__global__ void init_prep_kernel(const float* __restrict__ bias0) {
    int q = blockIdx.x * 256 + threadIdx.x;   // over NN*64 float4s
    if (q < NB) g_cnt[q] = 0;
    if (q >= NN * (DD / 4)) return;
    float4 b = *(const float4*)(bias0 + (q & 63) * 4);
    *(float4*)(g_Yroot + (size_t)q * 4) = b;
}

__global__ void count_kernel(const void* __restrict__ ei, const void* __restrict__ et) {
    int w = blockIdx.x * 256 + threadIdx.x;
    if (w >= EE) return;
    int src, dst, rel;
    if (!load_edge(ei, et, w, src, dst, rel)) return;
    atomicAdd(&g_cnt[(src >> 7) * RR + rel], 1);
}

// single-block exclusive scan of g_cnt -> g_ofs / g_fill (1024 thr x 4 buckets)
__global__ void scan_kernel() {
    __shared__ int s[1024];
    int t = threadIdx.x;
    int v[4], sum = 0;
#pragma unroll
    for (int i = 0; i < 4; i++) {
        int b = t * 4 + i;
        v[i] = (b < NB) ? g_cnt[b] : 0;
        sum += v[i];
    }
    s[t] = sum;
    __syncthreads();
    for (int off = 1; off < 1024; off <<= 1) {
        int x = (t >= off) ? s[t - off] : 0;
        __syncthreads();
        s[t] += x;
        __syncthreads();
    }
    int excl = s[t] - sum;
#pragma unroll
    for (int i = 0; i < 4; i++) {
        int b = t * 4 + i;
        if (b < NB) { g_ofs[b] = excl; g_fill[b] = excl; }
        excl += v[i];
    }
    if (t == 1023) g_ofs[NB] = excl;
}

__global__ void fill_kernel(const void* __restrict__ ei, const void* __restrict__ et) {
    int w = blockIdx.x * 256 + threadIdx.x;
    if (w >= EE) return;
    int src, dst, rel;
    if (!load_edge(ei, et, w, src, dst, rel)) return;
    int b = (src >> 7) * RR + rel;
    int pos = atomicAdd(&g_fill[b], 1);
    g_elist[pos] = ((uint32_t)(src & 127) << 17) | (uint32_t)dst;
}

// ---------------- conversion / activation ----------------
__global__ void conv_w_kernel(const float* __restrict__ weights, const float* __restrict__ roots) {
    size_t i = (size_t)blockIdx.x * 256 + threadIdx.x;
    if (i >= (size_t)3 * GG * DD * DD) return;
    int k = (int)(i & 255);
    int n = (int)((i >> 8) & 255);
    int lg = (int)(i >> 16);
    int l = lg / GG, g = lg % GG;
    float w = (g < 8) ? weights[(((size_t)(l * 8 + g)) * DD + k) * DD + n]
                      : roots[((size_t)l * DD + k) * DD + n];
    __nv_bfloat16 hi = __float2bfloat16(w);
    g_Whi[i] = hi;
    g_Wlo[i] = __float2bfloat16(w - __bfloat162float(hi));
}

__global__ void conv_x_kernel(const float* __restrict__ x) {
    int i = blockIdx.x * 256 + threadIdx.x;
    if (i >= NN * DD) return;
    float a = x[i];
    __nv_bfloat16 hi = __float2bfloat16(a);
    g_Ahi[i] = hi;
    g_Alo[i] = __float2bfloat16(a - __bfloat162float(hi));
}

// relu(g_Yroot) -> split bf16 hi/lo; re-init g_Yroot with NEXT layer's bias.
__global__ void act_split_kernel(const float* __restrict__ bias_next) {
    int q = blockIdx.x * 256 + threadIdx.x;         // over NN*DD/4
    if (q >= NN * (DD / 4)) return;
    float4 r = *(const float4*)(g_Yroot + (size_t)q * 4);
    float4 b = *(const float4*)(bias_next + (q & 63) * 4);
    *(float4*)(g_Yroot + (size_t)q * 4) = b;
    float v[4] = { fmaxf(r.x, 0.f), fmaxf(r.y, 0.f), fmaxf(r.z, 0.f), fmaxf(r.w, 0.f) };
    __nv_bfloat16 hi[4], lo[4];
#pragma unroll
    for (int i = 0; i < 4; i++) {
        hi[i] = __float2bfloat16(v[i]);
        lo[i] = __float2bfloat16(v[i] - __bfloat162float(hi[i]));
    }
    *(uint2*)(g_Ahi + (size_t)q * 4) = *(uint2*)hi;
    *(uint2*)(g_Alo + (size_t)q * 4) = *(uint2*)lo;
}

__global__ void act_final_kernel(float* __restrict__ out) {
    int q = blockIdx.x * 256 + threadIdx.x;         // over NN*DD/4
    if (q >= NN * (DD / 4)) return;
    float4 r = *(const float4*)(g_Yroot + (size_t)q * 4);
    float4 o;
    o.x = 1.f / (1.f + expf(-r.x));
    o.y = 1.f / (1.f + expf(-r.y));
    o.z = 1.f / (1.f + expf(-r.z));
    o.w = 1.f / (1.f + expf(-r.w));
    *(float4*)(out + (size_t)q * 4) = o;
}

// ---------------- HMMA GEMM + fused scatter epilogue ----------------
#define BM 128
#define BN 128
#define BK 32
#define STAGES 3
#define LDS_B 64
#define ARR (128 * LDS_B)
#define OFF_AHI 0
#define OFF_ALO ARR
#define OFF_BHI (2 * ARR)
#define OFF_BLO (3 * ARR)
#define STAGE_BYTES (4 * ARR)              // 32768
#define SMEM_TOTAL (STAGES * STAGE_BYTES)  // 98304 -> 2 CTAs/SM
#define CS_STRIDE 132                      // fp32 C staging row stride (padded)

#define CP_ASYNC16(dst, src, srcsz) \
    asm volatile("cp.async.cg.shared.global [%0], [%1], 16, %2;" \
                 :: "r"(dst), "l"(src), "r"(srcsz) : "memory")
#define CP_COMMIT() asm volatile("cp.async.commit_group;" ::: "memory")
#define CP_WAIT1()  asm volatile("cp.async.wait_group 1;" ::: "memory")

#define LDMX4(r, a) \
    asm volatile("ldmatrix.sync.aligned.m8n8.x4.shared.b16 {%0,%1,%2,%3}, [%4];" \
        : "=r"((r)[0]), "=r"((r)[1]), "=r"((r)[2]), "=r"((r)[3]) : "r"(a))

__device__ __forceinline__ uint32_t smem_u32(const void* p) {
    uint32_t a;
    asm("{ .reg .u64 t; cvta.to.shared.u64 t, %1; cvt.u32.u64 %0, t; }" : "=r"(a) : "l"(p));
    return a;
}
__device__ __forceinline__ uint32_t swz(uint32_t row, uint32_t j) {
    return row * LDS_B + ((j ^ ((row >> 1) & 3u)) << 4);
}
__device__ __forceinline__ void mma16816(float* d, const uint32_t* a, const uint32_t* b) {
    asm volatile(
        "mma.sync.aligned.m16n8k16.row.col.f32.bf16.bf16.f32 "
        "{%0,%1,%2,%3}, {%4,%5,%6,%7}, {%8,%9}, {%0,%1,%2,%3};"
        : "+f"(d[0]), "+f"(d[1]), "+f"(d[2]), "+f"(d[3])
        : "r"(a[0]), "r"(a[1]), "r"(a[2]), "r"(a[3]), "r"(b[0]), "r"(b[1]));
}

// Single launch, 18 n-tiles. ALL tiles accumulate atomically into g_Yroot
// (bias pre-initialized), so no ordering constraint between root & relations.
__global__ __launch_bounds__(256, 2)
void gemm_kernel(int lay) {
    extern __shared__ char smem[];
    const uint32_t sb = smem_u32(smem);
    const int t = threadIdx.x;
    const int wid = t >> 5, lane = t & 31;
    const int g = lane >> 2, t4 = lane & 3;
    const int m0 = blockIdx.x * BM;
    const int nt = blockIdx.y;
    const int warp_m = wid & 3, warp_n = wid >> 2;   // 4 x 2 warp grid

    const int group = nt >> 1, nh = nt & 1;          // group 0..7 rel, 8 root
    const __nv_bfloat16* Bh = g_Whi + ((size_t)(lay * GG + group) * DD + nh * 128) * DD;
    const __nv_bfloat16* Bl = g_Wlo + ((size_t)(lay * GG + group) * DD + nh * 128) * DD;

    float acc[2][8][4];
#pragma unroll
    for (int mi = 0; mi < 2; mi++)
#pragma unroll
        for (int nj = 0; nj < 8; nj++)
#pragma unroll
            for (int q = 0; q < 4; q++) acc[mi][nj][q] = 0.f;

    const int lr = lane & 7;
    const int l8 = (lane >> 3) & 1;
    const int l16 = (lane >> 4) & 1;

    auto load_stage = [&](int kt, int stage) {
        const int k0 = kt * BK;
        const uint32_t stb = sb + stage * STAGE_BYTES;
#pragma unroll
        for (int i = 0; i < 2; i++) {
            int c = t + i * 256;
            uint32_t row = (uint32_t)(c >> 2);
            uint32_t j = (uint32_t)(c & 3);
            uint32_t doff = swz(row, j);
            int col8 = (int)j * 8;
            int gr = m0 + (int)row;
            uint32_t asz = (gr < NN) ? 16u : 0u;
            int grc = (gr < NN) ? gr : 0;
            CP_ASYNC16(stb + OFF_AHI + doff, g_Ahi + (size_t)grc * DD + k0 + col8, asz);
            CP_ASYNC16(stb + OFF_ALO + doff, g_Alo + (size_t)grc * DD + k0 + col8, asz);
            CP_ASYNC16(stb + OFF_BHI + doff, Bh + (size_t)row * DD + k0 + col8, 16u);
            CP_ASYNC16(stb + OFF_BLO + doff, Bl + (size_t)row * DD + k0 + col8, 16u);
        }
    };

    load_stage(0, 0);
    CP_COMMIT();
    load_stage(1, 1);
    CP_COMMIT();

    const int NKT = DD / BK;   // 8  (NOT unrolled: keeps regs at 128, no spills)
    for (int kt = 0; kt < NKT; kt++) {
        CP_WAIT1();
        __syncthreads();
        if (kt + 2 < NKT) load_stage(kt + 2, (kt + 2) % STAGES);
        CP_COMMIT();

        const uint32_t stf = sb + (kt % STAGES) * STAGE_BYTES;
#pragma unroll
        for (int h = 0; h < 2; h++) {
            uint32_t ahi[2][4], alo[2][4], bhi[4][4], blo[4][4];
            {
                uint32_t jA = (uint32_t)(h * 2 + l16);
#pragma unroll
                for (int mi = 0; mi < 2; mi++) {
                    uint32_t arow = (uint32_t)(warp_m * 32 + mi * 16 + l8 * 8 + lr);
                    uint32_t ao = stf + swz(arow, jA);
                    LDMX4(ahi[mi], ao + OFF_AHI);
                    LDMX4(alo[mi], ao + OFF_ALO);
                }
            }
            {
                uint32_t jB = (uint32_t)(h * 2 + l8);
#pragma unroll
                for (int p = 0; p < 4; p++) {
                    uint32_t brow = (uint32_t)(warp_n * 64 + p * 16 + l16 * 8 + lr);
                    uint32_t bo = stf + swz(brow, jB);
                    LDMX4(bhi[p], bo + OFF_BHI);
                    LDMX4(blo[p], bo + OFF_BLO);
                }
            }
#pragma unroll
            for (int term = 0; term < 3; term++) {
#pragma unroll
                for (int mi = 0; mi < 2; mi++)
#pragma unroll
                    for (int p = 0; p < 4; p++) {
                        const uint32_t* af = (term == 2) ? alo[mi] : ahi[mi];
                        const uint32_t* bf = (term == 1) ? blo[p] : bhi[p];
                        mma16816(acc[mi][2 * p],     af, &bf[0]);
                        mma16816(acc[mi][2 * p + 1], af, &bf[2]);
                    }
            }
        }
    }

    // Unified epilogue: stage C tile to smem, then atomic-add rows into g_Yroot.
    __syncthreads();                       // all stage-buffer reads done
    float* cs = (float*)smem;              // [128][CS_STRIDE]
#pragma unroll
    for (int mi = 0; mi < 2; mi++) {
        int r0 = warp_m * 32 + mi * 16 + g;
#pragma unroll
        for (int nj = 0; nj < 8; nj++) {
            int cl = warp_n * 64 + nj * 8 + t4 * 2;
            *(float2*)(cs + r0 * CS_STRIDE + cl) =
                make_float2(acc[mi][nj][0], acc[mi][nj][1]);
            *(float2*)(cs + (r0 + 8) * CS_STRIDE + cl) =
                make_float2(acc[mi][nj][2], acc[mi][nj][3]);
        }
    }
    __syncthreads();

    if (group == 8) {
        // Root: identity scatter (row sl -> node m0+sl).
        for (int sl = wid; sl < BM; sl += 8) {
            int dst = m0 + sl;
            if (dst >= NN) break;
            float4 v = *(const float4*)(cs + sl * CS_STRIDE + lane * 4);
            float* p = g_Yroot + (size_t)dst * DD + nh * 128 + lane * 4;
            asm volatile("red.global.add.v4.f32 [%0], {%1, %2, %3, %4};"
                         :: "l"(p), "f"(v.x), "f"(v.y), "f"(v.z), "f"(v.w) : "memory");
        }
    } else {
        // Relations: walk this (src-block, rel) bucket.
        const int bid = blockIdx.x * RR + group;
        const int beg = g_ofs[bid], end = g_ofs[bid + 1];
        for (int i = beg + wid; i < end; i += 8) {
            uint32_t e = g_elist[i];
            int sl = (int)(e >> 17);
            int dst = (int)(e & 0x1FFFF);
            float4 v = *(const float4*)(cs + sl * CS_STRIDE + lane * 4);
            float* p = g_Yroot + (size_t)dst * DD + nh * 128 + lane * 4;
            asm volatile("red.global.add.v4.f32 [%0], {%1, %2, %3, %4};"
                         :: "l"(p), "f"(v.x), "f"(v.y), "f"(v.z), "f"(v.w) : "memory");
        }
    }
}

// ---------------- launch ----------------
extern "C" void kernel_launch(void* const* d_in, const int* in_sizes, int n_in,
                              void* d_out, int out_size) {
    const float* x       = (const float*)d_in[0];
    const float* weights = (const float*)d_in[1];
    const float* roots   = (const float*)d_in[2];
    const float* biases  = (const float*)d_in[3];
    const void*  ei      = d_in[4];
    const void*  et      = d_in[5];

    cudaFuncSetAttribute(gemm_kernel, cudaFuncAttributeMaxDynamicSharedMemorySize, SMEM_TOTAL);

    detect_kernel<<<1, 1>>>((const int*)ei);
    init_prep_kernel<<<(NN * DD / 4 + 255) / 256, 256>>>(biases);   // g_Yroot = bias0
    conv_w_kernel<<<(3 * GG * DD * DD + 255) / 256, 256>>>(weights, roots);
    conv_x_kernel<<<(NN * DD + 255) / 256, 256>>>(x);
    count_kernel<<<(EE + 255) / 256, 256>>>(ei, et);
    scan_kernel<<<1, 1024>>>();
    fill_kernel<<<(EE + 255) / 256, 256>>>(ei, et);

    for (int l = 0; l < 3; l++) {
        gemm_kernel<<<dim3(391, 18), 256, SMEM_TOTAL>>>(l);
        if (l < 2)
            act_split_kernel<<<(NN * DD / 4 + 255) / 256, 256>>>(biases + (size_t)(l + 1) * DD);
        else
            act_final_kernel<<<(NN * DD / 4 + 255) / 256, 256>>>((float*)d_out);
    }
}

// round 14
// speedup vs baseline: 2.3109x; 1.3383x over previous
#include <cuda_runtime.h>
#include <cuda_fp16.h>
#include <cstdint>
#include <cstddef>

#define NN 50000
#define DD 256
#define RR 8
#define EE 300000
#define GG 9            // 8 relations + root
#define NB (391 * 8)    // edge buckets: (src block) x relation

// ---------------- device scratch ----------------
__device__ __align__(256) float g_Yroot[(size_t)NN * DD];                 // single accumulator
__device__ __align__(256) __half g_A16[(size_t)NN * DD];                  // activations, fp16
__device__ __align__(256) __half g_Wh[(size_t)3 * GG * DD * DD];          // [l][g][n][k] weight hi
__device__ __align__(256) __half g_Wl[(size_t)3 * GG * DD * DD];          // weight lo
__device__ int g_idx64;
__device__ int g_cnt[NB];
__device__ int g_ofs[NB + 1];
__device__ int g_fill[NB];
__device__ uint32_t g_elist[EE];

// ---------------- edge helpers ----------------
__device__ __forceinline__ bool load_edge(const void* ei, const void* et, int w,
                                          int& src, int& dst, int& rel) {
    long long s, d, r;
    if (g_idx64) {
        s = ((const long long*)ei)[w];
        d = ((const long long*)ei)[EE + w];
        r = ((const long long*)et)[w];
    } else {
        s = ((const int*)ei)[w];
        d = ((const int*)ei)[EE + w];
        r = ((const int*)et)[w];
    }
    if ((unsigned long long)s >= NN || (unsigned long long)d >= NN ||
        (unsigned long long)r >= RR) return false;
    src = (int)s; dst = (int)d; rel = (int)r;
    return true;
}

__global__ void detect_kernel(const int* __restrict__ ei32) {
    int allzero = 1;
    for (int i = 1; i < 64; i += 2)
        if (ei32[i] != 0) allzero = 0;
    g_idx64 = allzero;
}

// Init g_Yroot with layer-0 bias (runs every graph replay) + zero bucket counts.
__global__ void init_prep_kernel(const float* __restrict__ bias0) {
    int q = blockIdx.x * 256 + threadIdx.x;   // over NN*64 float4s
    if (q < NB) g_cnt[q] = 0;
    if (q >= NN * (DD / 4)) return;
    float4 b = *(const float4*)(bias0 + (q & 63) * 4);
    *(float4*)(g_Yroot + (size_t)q * 4) = b;
}

__global__ void count_kernel(const void* __restrict__ ei, const void* __restrict__ et) {
    int w = blockIdx.x * 256 + threadIdx.x;
    if (w >= EE) return;
    int src, dst, rel;
    if (!load_edge(ei, et, w, src, dst, rel)) return;
    atomicAdd(&g_cnt[(src >> 7) * RR + rel], 1);
}

// single-block exclusive scan of g_cnt -> g_ofs / g_fill (1024 thr x 4 buckets)
__global__ void scan_kernel() {
    __shared__ int s[1024];
    int t = threadIdx.x;
    int v[4], sum = 0;
#pragma unroll
    for (int i = 0; i < 4; i++) {
        int b = t * 4 + i;
        v[i] = (b < NB) ? g_cnt[b] : 0;
        sum += v[i];
    }
    s[t] = sum;
    __syncthreads();
    for (int off = 1; off < 1024; off <<= 1) {
        int x = (t >= off) ? s[t - off] : 0;
        __syncthreads();
        s[t] += x;
        __syncthreads();
    }
    int excl = s[t] - sum;
#pragma unroll
    for (int i = 0; i < 4; i++) {
        int b = t * 4 + i;
        if (b < NB) { g_ofs[b] = excl; g_fill[b] = excl; }
        excl += v[i];
    }
    if (t == 1023) g_ofs[NB] = excl;
}

__global__ void fill_kernel(const void* __restrict__ ei, const void* __restrict__ et) {
    int w = blockIdx.x * 256 + threadIdx.x;
    if (w >= EE) return;
    int src, dst, rel;
    if (!load_edge(ei, et, w, src, dst, rel)) return;
    int b = (src >> 7) * RR + rel;
    int pos = atomicAdd(&g_fill[b], 1);
    g_elist[pos] = ((uint32_t)(src & 127) << 17) | (uint32_t)dst;
}

// ---------------- conversion / activation ----------------
// Weights split into fp16 hi+lo (22-bit effective), transposed to [l][g][n][k].
__global__ void conv_w_kernel(const float* __restrict__ weights, const float* __restrict__ roots) {
    size_t i = (size_t)blockIdx.x * 256 + threadIdx.x;
    if (i >= (size_t)3 * GG * DD * DD) return;
    int k = (int)(i & 255);
    int n = (int)((i >> 8) & 255);
    int lg = (int)(i >> 16);
    int l = lg / GG, g = lg % GG;
    float w = (g < 8) ? weights[(((size_t)(l * 8 + g)) * DD + k) * DD + n]
                      : roots[((size_t)l * DD + k) * DD + n];
    __half hi = __float2half_rn(w);
    g_Wh[i] = hi;
    g_Wl[i] = __float2half_rn(w - __half2float(hi));
}

__global__ void conv_x_kernel(const float* __restrict__ x) {
    int i = blockIdx.x * 256 + threadIdx.x;
    if (i >= NN * DD) return;
    g_A16[i] = __float2half_rn(x[i]);
}

// relu(g_Yroot) -> fp16 A; re-init g_Yroot with NEXT layer's bias.
__global__ void act_split_kernel(const float* __restrict__ bias_next) {
    int q = blockIdx.x * 256 + threadIdx.x;         // over NN*DD/4
    if (q >= NN * (DD / 4)) return;
    float4 r = *(const float4*)(g_Yroot + (size_t)q * 4);
    float4 b = *(const float4*)(bias_next + (q & 63) * 4);
    *(float4*)(g_Yroot + (size_t)q * 4) = b;
    __half h[4];
    h[0] = __float2half_rn(fmaxf(r.x, 0.f));
    h[1] = __float2half_rn(fmaxf(r.y, 0.f));
    h[2] = __float2half_rn(fmaxf(r.z, 0.f));
    h[3] = __float2half_rn(fmaxf(r.w, 0.f));
    *(uint2*)(g_A16 + (size_t)q * 4) = *(uint2*)h;
}

__global__ void act_final_kernel(float* __restrict__ out) {
    int q = blockIdx.x * 256 + threadIdx.x;         // over NN*DD/4
    if (q >= NN * (DD / 4)) return;
    float4 r = *(const float4*)(g_Yroot + (size_t)q * 4);
    float4 o;
    o.x = 1.f / (1.f + expf(-r.x));
    o.y = 1.f / (1.f + expf(-r.y));
    o.z = 1.f / (1.f + expf(-r.z));
    o.w = 1.f / (1.f + expf(-r.w));
    *(float4*)(out + (size_t)q * 4) = o;
}

// ---------------- HMMA GEMM + fused scatter epilogue ----------------
// fp16 2-term: C = A16 * Whi + A16 * Wlo  (weights split, activations rounded)
#define BM 128
#define BN 128
#define BK 32
#define STAGES 4
#define LDS_B 64
#define ARR (128 * LDS_B)                  // 8192 bytes per 128x32 fp16 array
#define OFF_A16 0
#define OFF_BHI ARR
#define OFF_BLO (2 * ARR)
#define STAGE_BYTES (3 * ARR)              // 24576
#define SMEM_TOTAL (STAGES * STAGE_BYTES)  // 98304 -> 2 CTAs/SM
#define CS_STRIDE 132                      // fp32 C staging row stride (padded)

#define CP_ASYNC16(dst, src, srcsz) \
    asm volatile("cp.async.cg.shared.global [%0], [%1], 16, %2;" \
                 :: "r"(dst), "l"(src), "r"(srcsz) : "memory")
#define CP_COMMIT() asm volatile("cp.async.commit_group;" ::: "memory")
#define CP_WAIT2()  asm volatile("cp.async.wait_group 2;" ::: "memory")

#define LDMX4(r, a) \
    asm volatile("ldmatrix.sync.aligned.m8n8.x4.shared.b16 {%0,%1,%2,%3}, [%4];" \
        : "=r"((r)[0]), "=r"((r)[1]), "=r"((r)[2]), "=r"((r)[3]) : "r"(a))

__device__ __forceinline__ uint32_t smem_u32(const void* p) {
    uint32_t a;
    asm("{ .reg .u64 t; cvta.to.shared.u64 t, %1; cvt.u32.u64 %0, t; }" : "=r"(a) : "l"(p));
    return a;
}
__device__ __forceinline__ uint32_t swz(uint32_t row, uint32_t j) {
    return row * LDS_B + ((j ^ ((row >> 1) & 3u)) << 4);
}
__device__ __forceinline__ void mma16816(float* d, const uint32_t* a, const uint32_t* b) {
    asm volatile(
        "mma.sync.aligned.m16n8k16.row.col.f32.f16.f16.f32 "
        "{%0,%1,%2,%3}, {%4,%5,%6,%7}, {%8,%9}, {%0,%1,%2,%3};"
        : "+f"(d[0]), "+f"(d[1]), "+f"(d[2]), "+f"(d[3])
        : "r"(a[0]), "r"(a[1]), "r"(a[2]), "r"(a[3]), "r"(b[0]), "r"(b[1]));
}

// Single launch, 18 n-tiles. ALL tiles accumulate atomically into g_Yroot.
__global__ __launch_bounds__(256, 2)
void gemm_kernel(int lay) {
    extern __shared__ char smem[];
    const uint32_t sb = smem_u32(smem);
    const int t = threadIdx.x;
    const int wid = t >> 5, lane = t & 31;
    const int g = lane >> 2, t4 = lane & 3;
    const int m0 = blockIdx.x * BM;
    const int nt = blockIdx.y;
    const int warp_m = wid & 3, warp_n = wid >> 2;   // 4 x 2 warp grid

    const int group = nt >> 1, nh = nt & 1;          // group 0..7 rel, 8 root
    const __half* Bh = g_Wh + ((size_t)(lay * GG + group) * DD + nh * 128) * DD;
    const __half* Bl = g_Wl + ((size_t)(lay * GG + group) * DD + nh * 128) * DD;

    float acc[2][8][4];
#pragma unroll
    for (int mi = 0; mi < 2; mi++)
#pragma unroll
        for (int nj = 0; nj < 8; nj++)
#pragma unroll
            for (int q = 0; q < 4; q++) acc[mi][nj][q] = 0.f;

    const int lr = lane & 7;
    const int l8 = (lane >> 3) & 1;
    const int l16 = (lane >> 4) & 1;

    auto load_stage = [&](int kt, int stage) {
        const int k0 = kt * BK;
        const uint32_t stb = sb + stage * STAGE_BYTES;
#pragma unroll
        for (int i = 0; i < 2; i++) {
            int c = t + i * 256;
            uint32_t row = (uint32_t)(c >> 2);
            uint32_t j = (uint32_t)(c & 3);
            uint32_t doff = swz(row, j);
            int col8 = (int)j * 8;
            int gr = m0 + (int)row;
            uint32_t asz = (gr < NN) ? 16u : 0u;
            int grc = (gr < NN) ? gr : 0;
            CP_ASYNC16(stb + OFF_A16 + doff, g_A16 + (size_t)grc * DD + k0 + col8, asz);
            CP_ASYNC16(stb + OFF_BHI + doff, Bh + (size_t)row * DD + k0 + col8, 16u);
            CP_ASYNC16(stb + OFF_BLO + doff, Bl + (size_t)row * DD + k0 + col8, 16u);
        }
    };

    load_stage(0, 0);
    CP_COMMIT();
    load_stage(1, 1);
    CP_COMMIT();
    load_stage(2, 2);
    CP_COMMIT();

    const int NKT = DD / BK;   // 8  (NOT unrolled: keeps regs capped, no spills)
    for (int kt = 0; kt < NKT; kt++) {
        CP_WAIT2();            // stage kt landed
        __syncthreads();       // protects buffer (kt+3)%4 (computed at kt-1)
        if (kt + 3 < NKT) load_stage(kt + 3, (kt + 3) % STAGES);
        CP_COMMIT();

        const uint32_t stf = sb + (kt % STAGES) * STAGE_BYTES;
#pragma unroll
        for (int h = 0; h < 2; h++) {
            uint32_t af[2][4], bhi[4][4], blo[4][4];
            {
                uint32_t jA = (uint32_t)(h * 2 + l16);
#pragma unroll
                for (int mi = 0; mi < 2; mi++) {
                    uint32_t arow = (uint32_t)(warp_m * 32 + mi * 16 + l8 * 8 + lr);
                    LDMX4(af[mi], stf + swz(arow, jA) + OFF_A16);
                }
            }
            {
                uint32_t jB = (uint32_t)(h * 2 + l8);
#pragma unroll
                for (int p = 0; p < 4; p++) {
                    uint32_t brow = (uint32_t)(warp_n * 64 + p * 16 + l16 * 8 + lr);
                    uint32_t bo = stf + swz(brow, jB);
                    LDMX4(bhi[p], bo + OFF_BHI);
                    LDMX4(blo[p], bo + OFF_BLO);
                }
            }
            // 2 terms; RAW distance on each acc group = 16 MMAs.
#pragma unroll
            for (int term = 0; term < 2; term++) {
#pragma unroll
                for (int mi = 0; mi < 2; mi++)
#pragma unroll
                    for (int p = 0; p < 4; p++) {
                        const uint32_t* bf = term ? blo[p] : bhi[p];
                        mma16816(acc[mi][2 * p],     af[mi], &bf[0]);
                        mma16816(acc[mi][2 * p + 1], af[mi], &bf[2]);
                    }
            }
        }
    }

    // Unified epilogue: stage C tile to smem, then atomic-add rows into g_Yroot.
    __syncthreads();                       // all stage-buffer reads done
    float* cs = (float*)smem;              // [128][CS_STRIDE]
#pragma unroll
    for (int mi = 0; mi < 2; mi++) {
        int r0 = warp_m * 32 + mi * 16 + g;
#pragma unroll
        for (int nj = 0; nj < 8; nj++) {
            int cl = warp_n * 64 + nj * 8 + t4 * 2;
            *(float2*)(cs + r0 * CS_STRIDE + cl) =
                make_float2(acc[mi][nj][0], acc[mi][nj][1]);
            *(float2*)(cs + (r0 + 8) * CS_STRIDE + cl) =
                make_float2(acc[mi][nj][2], acc[mi][nj][3]);
        }
    }
    __syncthreads();

    if (group == 8) {
        // Root: identity scatter (row sl -> node m0+sl).
        for (int sl = wid; sl < BM; sl += 8) {
            int dst = m0 + sl;
            if (dst >= NN) break;
            float4 v = *(const float4*)(cs + sl * CS_STRIDE + lane * 4);
            float* p = g_Yroot + (size_t)dst * DD + nh * 128 + lane * 4;
            asm volatile("red.global.add.v4.f32 [%0], {%1, %2, %3, %4};"
                         :: "l"(p), "f"(v.x), "f"(v.y), "f"(v.z), "f"(v.w) : "memory");
        }
    } else {
        // Relations: walk this (src-block, rel) bucket.
        const int bid = blockIdx.x * RR + group;
        const int beg = g_ofs[bid], end = g_ofs[bid + 1];
        for (int i = beg + wid; i < end; i += 8) {
            uint32_t e = g_elist[i];
            int sl = (int)(e >> 17);
            int dst = (int)(e & 0x1FFFF);
            float4 v = *(const float4*)(cs + sl * CS_STRIDE + lane * 4);
            float* p = g_Yroot + (size_t)dst * DD + nh * 128 + lane * 4;
            asm volatile("red.global.add.v4.f32 [%0], {%1, %2, %3, %4};"
                         :: "l"(p), "f"(v.x), "f"(v.y), "f"(v.z), "f"(v.w) : "memory");
        }
    }
}

// ---------------- launch ----------------
extern "C" void kernel_launch(void* const* d_in, const int* in_sizes, int n_in,
                              void* d_out, int out_size) {
    const float* x       = (const float*)d_in[0];
    const float* weights = (const float*)d_in[1];
    const float* roots   = (const float*)d_in[2];
    const float* biases  = (const float*)d_in[3];
    const void*  ei      = d_in[4];
    const void*  et      = d_in[5];

    cudaFuncSetAttribute(gemm_kernel, cudaFuncAttributeMaxDynamicSharedMemorySize, SMEM_TOTAL);

    detect_kernel<<<1, 1>>>((const int*)ei);
    init_prep_kernel<<<(NN * DD / 4 + 255) / 256, 256>>>(biases);   // g_Yroot = bias0
    conv_w_kernel<<<(3 * GG * DD * DD + 255) / 256, 256>>>(weights, roots);
    conv_x_kernel<<<(NN * DD + 255) / 256, 256>>>(x);
    count_kernel<<<(EE + 255) / 256, 256>>>(ei, et);
    scan_kernel<<<1, 1024>>>();
    fill_kernel<<<(EE + 255) / 256, 256>>>(ei, et);

    for (int l = 0; l < 3; l++) {
        gemm_kernel<<<dim3(391, 18), 256, SMEM_TOTAL>>>(l);
        if (l < 2)
            act_split_kernel<<<(NN * DD / 4 + 255) / 256, 256>>>(biases + (size_t)(l + 1) * DD);
        else
            act_final_kernel<<<(NN * DD / 4 + 255) / 256, 256>>>((float*)d_out);
    }
}

// round 15
// speedup vs baseline: 2.3624x; 1.0223x over previous
#include <cuda_runtime.h>
#include <cuda_fp16.h>
#include <cstdint>
#include <cstddef>

#define NN 50000
#define DD 256
#define RR 8
#define EE 300000
#define GG 9            // 8 relations + root
#define NB (391 * 8)    // edge buckets: (src block) x relation

// ---------------- device scratch ----------------
__device__ __align__(256) float g_Yroot[(size_t)NN * DD];                 // single accumulator
__device__ __align__(256) __half g_A16[(size_t)NN * DD];                  // activations, fp16
__device__ __align__(256) __half g_Wh[(size_t)3 * GG * DD * DD];          // [l][g][n][k] weight hi
__device__ __align__(256) __half g_Wl[(size_t)3 * GG * DD * DD];          // weight lo
__device__ int g_idx64;
__device__ int g_cnt[NB];
__device__ int g_ofs[NB + 1];
__device__ int g_fill[NB];
__device__ uint32_t g_elist[EE];

// ---------------- edge helpers ----------------
__device__ __forceinline__ bool load_edge(const void* ei, const void* et, int w,
                                          int& src, int& dst, int& rel) {
    long long s, d, r;
    if (g_idx64) {
        s = ((const long long*)ei)[w];
        d = ((const long long*)ei)[EE + w];
        r = ((const long long*)et)[w];
    } else {
        s = ((const int*)ei)[w];
        d = ((const int*)ei)[EE + w];
        r = ((const int*)et)[w];
    }
    if ((unsigned long long)s >= NN || (unsigned long long)d >= NN ||
        (unsigned long long)r >= RR) return false;
    src = (int)s; dst = (int)d; rel = (int)r;
    return true;
}

// Fused prep: dtype detect + bucket-count zero + g_Yroot=bias0 + x->fp16.
// Grid covers NN*DD/4 float4 groups.
__global__ void prep_kernel(const float* __restrict__ x,
                            const float* __restrict__ bias0,
                            const int* __restrict__ ei32) {
    int q = blockIdx.x * 256 + threadIdx.x;
    if (q == 0) {                     // int64 edge dtype iff odd int32 words all zero
        int allzero = 1;
        for (int i = 1; i < 64; i += 2)
            if (ei32[i] != 0) allzero = 0;
        g_idx64 = allzero;
    }
    if (q < NB) g_cnt[q] = 0;
    if (q >= NN * (DD / 4)) return;
    float4 b = *(const float4*)(bias0 + (q & 63) * 4);
    *(float4*)(g_Yroot + (size_t)q * 4) = b;
    float4 xv = *(const float4*)(x + (size_t)q * 4);
    __half h[4];
    h[0] = __float2half_rn(xv.x);
    h[1] = __float2half_rn(xv.y);
    h[2] = __float2half_rn(xv.z);
    h[3] = __float2half_rn(xv.w);
    *(uint2*)(g_A16 + (size_t)q * 4) = *(uint2*)h;
}

__global__ void count_kernel(const void* __restrict__ ei, const void* __restrict__ et) {
    int w = blockIdx.x * 256 + threadIdx.x;
    if (w >= EE) return;
    int src, dst, rel;
    if (!load_edge(ei, et, w, src, dst, rel)) return;
    atomicAdd(&g_cnt[(src >> 7) * RR + rel], 1);
}

// single-block exclusive scan of g_cnt -> g_ofs / g_fill (1024 thr x 4 buckets)
__global__ void scan_kernel() {
    __shared__ int s[1024];
    int t = threadIdx.x;
    int v[4], sum = 0;
#pragma unroll
    for (int i = 0; i < 4; i++) {
        int b = t * 4 + i;
        v[i] = (b < NB) ? g_cnt[b] : 0;
        sum += v[i];
    }
    s[t] = sum;
    __syncthreads();
    for (int off = 1; off < 1024; off <<= 1) {
        int x = (t >= off) ? s[t - off] : 0;
        __syncthreads();
        s[t] += x;
        __syncthreads();
    }
    int excl = s[t] - sum;
#pragma unroll
    for (int i = 0; i < 4; i++) {
        int b = t * 4 + i;
        if (b < NB) { g_ofs[b] = excl; g_fill[b] = excl; }
        excl += v[i];
    }
    if (t == 1023) g_ofs[NB] = excl;
}

__global__ void fill_kernel(const void* __restrict__ ei, const void* __restrict__ et) {
    int w = blockIdx.x * 256 + threadIdx.x;
    if (w >= EE) return;
    int src, dst, rel;
    if (!load_edge(ei, et, w, src, dst, rel)) return;
    int b = (src >> 7) * RR + rel;
    int pos = atomicAdd(&g_fill[b], 1);
    g_elist[pos] = ((uint32_t)(src & 127) << 17) | (uint32_t)dst;
}

// ---------------- conversion / activation ----------------
// Weights split into fp16 hi+lo (22-bit effective), transposed to [l][g][n][k].
__global__ void conv_w_kernel(const float* __restrict__ weights, const float* __restrict__ roots) {
    size_t i = (size_t)blockIdx.x * 256 + threadIdx.x;
    if (i >= (size_t)3 * GG * DD * DD) return;
    int k = (int)(i & 255);
    int n = (int)((i >> 8) & 255);
    int lg = (int)(i >> 16);
    int l = lg / GG, g = lg % GG;
    float w = (g < 8) ? weights[(((size_t)(l * 8 + g)) * DD + k) * DD + n]
                      : roots[((size_t)l * DD + k) * DD + n];
    __half hi = __float2half_rn(w);
    g_Wh[i] = hi;
    g_Wl[i] = __float2half_rn(w - __half2float(hi));
}

// relu(g_Yroot) -> fp16 A; re-init g_Yroot with NEXT layer's bias.
__global__ void act_split_kernel(const float* __restrict__ bias_next) {
    int q = blockIdx.x * 256 + threadIdx.x;         // over NN*DD/4
    if (q >= NN * (DD / 4)) return;
    float4 r = *(const float4*)(g_Yroot + (size_t)q * 4);
    float4 b = *(const float4*)(bias_next + (q & 63) * 4);
    *(float4*)(g_Yroot + (size_t)q * 4) = b;
    __half h[4];
    h[0] = __float2half_rn(fmaxf(r.x, 0.f));
    h[1] = __float2half_rn(fmaxf(r.y, 0.f));
    h[2] = __float2half_rn(fmaxf(r.z, 0.f));
    h[3] = __float2half_rn(fmaxf(r.w, 0.f));
    *(uint2*)(g_A16 + (size_t)q * 4) = *(uint2*)h;
}

__global__ void act_final_kernel(float* __restrict__ out) {
    int q = blockIdx.x * 256 + threadIdx.x;         // over NN*DD/4
    if (q >= NN * (DD / 4)) return;
    float4 r = *(const float4*)(g_Yroot + (size_t)q * 4);
    float4 o;
    o.x = 1.f / (1.f + expf(-r.x));
    o.y = 1.f / (1.f + expf(-r.y));
    o.z = 1.f / (1.f + expf(-r.z));
    o.w = 1.f / (1.f + expf(-r.w));
    *(float4*)(out + (size_t)q * 4) = o;
}

// ---------------- HMMA GEMM + fused scatter epilogue ----------------
// fp16 2-term: C = A16 * Whi + A16 * Wlo  (weights split, activations rounded)
#define BM 128
#define BN 128
#define BK 32
#define STAGES 4
#define LDS_B 64
#define ARR (128 * LDS_B)                  // 8192 bytes per 128x32 fp16 array
#define OFF_A16 0
#define OFF_BHI ARR
#define OFF_BLO (2 * ARR)
#define STAGE_BYTES (3 * ARR)              // 24576
#define SMEM_TOTAL (STAGES * STAGE_BYTES)  // 98304 -> 2 CTAs/SM
#define CS_STRIDE 132                      // fp32 C staging row stride (padded)

#define CP_ASYNC16(dst, src, srcsz) \
    asm volatile("cp.async.cg.shared.global [%0], [%1], 16, %2;" \
                 :: "r"(dst), "l"(src), "r"(srcsz) : "memory")
#define CP_COMMIT() asm volatile("cp.async.commit_group;" ::: "memory")
#define CP_WAIT2()  asm volatile("cp.async.wait_group 2;" ::: "memory")

#define LDMX4(r, a) \
    asm volatile("ldmatrix.sync.aligned.m8n8.x4.shared.b16 {%0,%1,%2,%3}, [%4];" \
        : "=r"((r)[0]), "=r"((r)[1]), "=r"((r)[2]), "=r"((r)[3]) : "r"(a))

__device__ __forceinline__ uint32_t smem_u32(const void* p) {
    uint32_t a;
    asm("{ .reg .u64 t; cvta.to.shared.u64 t, %1; cvt.u32.u64 %0, t; }" : "=r"(a) : "l"(p));
    return a;
}
__device__ __forceinline__ uint32_t swz(uint32_t row, uint32_t j) {
    return row * LDS_B + ((j ^ ((row >> 1) & 3u)) << 4);
}
__device__ __forceinline__ void mma16816(float* d, const uint32_t* a, const uint32_t* b) {
    asm volatile(
        "mma.sync.aligned.m16n8k16.row.col.f32.f16.f16.f32 "
        "{%0,%1,%2,%3}, {%4,%5,%6,%7}, {%8,%9}, {%0,%1,%2,%3};"
        : "+f"(d[0]), "+f"(d[1]), "+f"(d[2]), "+f"(d[3])
        : "r"(a[0]), "r"(a[1]), "r"(a[2]), "r"(a[3]), "r"(b[0]), "r"(b[1]));
}

// Single launch, 18 n-tiles. ALL tiles accumulate atomically into g_Yroot.
__global__ __launch_bounds__(256, 2)
void gemm_kernel(int lay) {
    extern __shared__ char smem[];
    const uint32_t sb = smem_u32(smem);
    const int t = threadIdx.x;
    const int wid = t >> 5, lane = t & 31;
    const int g = lane >> 2, t4 = lane & 3;
    const int m0 = blockIdx.x * BM;
    const int nt = blockIdx.y;
    const int warp_m = wid & 3, warp_n = wid >> 2;   // 4 x 2 warp grid

    const int group = nt >> 1, nh = nt & 1;          // group 0..7 rel, 8 root
    const __half* Bh = g_Wh + ((size_t)(lay * GG + group) * DD + nh * 128) * DD;
    const __half* Bl = g_Wl + ((size_t)(lay * GG + group) * DD + nh * 128) * DD;

    float acc[2][8][4];
#pragma unroll
    for (int mi = 0; mi < 2; mi++)
#pragma unroll
        for (int nj = 0; nj < 8; nj++)
#pragma unroll
            for (int q = 0; q < 4; q++) acc[mi][nj][q] = 0.f;

    const int lr = lane & 7;
    const int l8 = (lane >> 3) & 1;
    const int l16 = (lane >> 4) & 1;

    auto load_stage = [&](int kt, int stage) {
        const int k0 = kt * BK;
        const uint32_t stb = sb + stage * STAGE_BYTES;
#pragma unroll
        for (int i = 0; i < 2; i++) {
            int c = t + i * 256;
            uint32_t row = (uint32_t)(c >> 2);
            uint32_t j = (uint32_t)(c & 3);
            uint32_t doff = swz(row, j);
            int col8 = (int)j * 8;
            int gr = m0 + (int)row;
            uint32_t asz = (gr < NN) ? 16u : 0u;
            int grc = (gr < NN) ? gr : 0;
            CP_ASYNC16(stb + OFF_A16 + doff, g_A16 + (size_t)grc * DD + k0 + col8, asz);
            CP_ASYNC16(stb + OFF_BHI + doff, Bh + (size_t)row * DD + k0 + col8, 16u);
            CP_ASYNC16(stb + OFF_BLO + doff, Bl + (size_t)row * DD + k0 + col8, 16u);
        }
    };

    load_stage(0, 0);
    CP_COMMIT();
    load_stage(1, 1);
    CP_COMMIT();
    load_stage(2, 2);
    CP_COMMIT();

    const int NKT = DD / BK;   // 8  (NOT unrolled: keeps regs capped, no spills)
    for (int kt = 0; kt < NKT; kt++) {
        CP_WAIT2();            // stage kt landed
        __syncthreads();       // protects buffer (kt+3)%4 (computed at kt-1)
        if (kt + 3 < NKT) load_stage(kt + 3, (kt + 3) % STAGES);
        CP_COMMIT();

        const uint32_t stf = sb + (kt % STAGES) * STAGE_BYTES;
#pragma unroll
        for (int h = 0; h < 2; h++) {
            uint32_t af[2][4], bhi[4][4], blo[4][4];
            {
                uint32_t jA = (uint32_t)(h * 2 + l16);
#pragma unroll
                for (int mi = 0; mi < 2; mi++) {
                    uint32_t arow = (uint32_t)(warp_m * 32 + mi * 16 + l8 * 8 + lr);
                    LDMX4(af[mi], stf + swz(arow, jA) + OFF_A16);
                }
            }
            {
                uint32_t jB = (uint32_t)(h * 2 + l8);
#pragma unroll
                for (int p = 0; p < 4; p++) {
                    uint32_t brow = (uint32_t)(warp_n * 64 + p * 16 + l16 * 8 + lr);
                    uint32_t bo = stf + swz(brow, jB);
                    LDMX4(bhi[p], bo + OFF_BHI);
                    LDMX4(blo[p], bo + OFF_BLO);
                }
            }
            // 2 terms; RAW distance on each acc group = 16 MMAs.
#pragma unroll
            for (int term = 0; term < 2; term++) {
#pragma unroll
                for (int mi = 0; mi < 2; mi++)
#pragma unroll
                    for (int p = 0; p < 4; p++) {
                        const uint32_t* bf = term ? blo[p] : bhi[p];
                        mma16816(acc[mi][2 * p],     af[mi], &bf[0]);
                        mma16816(acc[mi][2 * p + 1], af[mi], &bf[2]);
                    }
            }
        }
    }

    // Unified epilogue: stage C tile to smem, then atomic-add rows into g_Yroot.
    __syncthreads();                       // all stage-buffer reads done
    float* cs = (float*)smem;              // [128][CS_STRIDE]
#pragma unroll
    for (int mi = 0; mi < 2; mi++) {
        int r0 = warp_m * 32 + mi * 16 + g;
#pragma unroll
        for (int nj = 0; nj < 8; nj++) {
            int cl = warp_n * 64 + nj * 8 + t4 * 2;
            *(float2*)(cs + r0 * CS_STRIDE + cl) =
                make_float2(acc[mi][nj][0], acc[mi][nj][1]);
            *(float2*)(cs + (r0 + 8) * CS_STRIDE + cl) =
                make_float2(acc[mi][nj][2], acc[mi][nj][3]);
        }
    }
    __syncthreads();

    if (group == 8) {
        // Root: identity scatter (row sl -> node m0+sl).
        for (int sl = wid; sl < BM; sl += 8) {
            int dst = m0 + sl;
            if (dst >= NN) break;
            float4 v = *(const float4*)(cs + sl * CS_STRIDE + lane * 4);
            float* p = g_Yroot + (size_t)dst * DD + nh * 128 + lane * 4;
            asm volatile("red.global.add.v4.f32 [%0], {%1, %2, %3, %4};"
                         :: "l"(p), "f"(v.x), "f"(v.y), "f"(v.z), "f"(v.w) : "memory");
        }
    } else {
        // Relations: walk this (src-block, rel) bucket.
        const int bid = blockIdx.x * RR + group;
        const int beg = g_ofs[bid], end = g_ofs[bid + 1];
        for (int i = beg + wid; i < end; i += 8) {
            uint32_t e = g_elist[i];
            int sl = (int)(e >> 17);
            int dst = (int)(e & 0x1FFFF);
            float4 v = *(const float4*)(cs + sl * CS_STRIDE + lane * 4);
            float* p = g_Yroot + (size_t)dst * DD + nh * 128 + lane * 4;
            asm volatile("red.global.add.v4.f32 [%0], {%1, %2, %3, %4};"
                         :: "l"(p), "f"(v.x), "f"(v.y), "f"(v.z), "f"(v.w) : "memory");
        }
    }
}

// ---------------- launch ----------------
extern "C" void kernel_launch(void* const* d_in, const int* in_sizes, int n_in,
                              void* d_out, int out_size) {
    const float* x       = (const float*)d_in[0];
    const float* weights = (const float*)d_in[1];
    const float* roots   = (const float*)d_in[2];
    const float* biases  = (const float*)d_in[3];
    const void*  ei      = d_in[4];
    const void*  et      = d_in[5];

    cudaFuncSetAttribute(gemm_kernel, cudaFuncAttributeMaxDynamicSharedMemorySize, SMEM_TOTAL);

    prep_kernel<<<(NN * DD / 4 + 255) / 256, 256>>>(x, biases, (const int*)ei);
    conv_w_kernel<<<(3 * GG * DD * DD + 255) / 256, 256>>>(weights, roots);
    count_kernel<<<(EE + 255) / 256, 256>>>(ei, et);
    scan_kernel<<<1, 1024>>>();
    fill_kernel<<<(EE + 255) / 256, 256>>>(ei, et);

    for (int l = 0; l < 3; l++) {
        gemm_kernel<<<dim3(391, 18), 256, SMEM_TOTAL>>>(l);
        if (l < 2)
            act_split_kernel<<<(NN * DD / 4 + 255) / 256, 256>>>(biases + (size_t)(l + 1) * DD);
        else
            act_final_kernel<<<(NN * DD / 4 + 255) / 256, 256>>>((float*)d_out);
    }
}

// round 16
// speedup vs baseline: 3.6844x; 1.5596x over previous
#include <cuda_runtime.h>
#include <cuda_fp16.h>
#include <cstdint>
#include <cstddef>

#define NN 50000
#define DD 256
#define RR 8
#define EE 300000
#define GG 9            // 8 relations + root
#define NB (391 * 8)    // edge buckets: (src block) x relation

// ---------------- device scratch ----------------
__device__ __align__(256) float g_Yroot[(size_t)NN * DD];                 // single accumulator
__device__ __align__(256) __half g_A16[(size_t)NN * DD];                  // activations, fp16
__device__ __align__(256) __half g_W16[(size_t)3 * GG * DD * DD];         // [l][g][n][k] weights fp16
__device__ int g_idx64;
__device__ int g_cnt[NB];
__device__ int g_ofs[NB + 1];
__device__ int g_fill[NB];
__device__ uint32_t g_elist[EE];

// ---------------- edge helpers ----------------
__device__ __forceinline__ bool load_edge(const void* ei, const void* et, int w,
                                          int& src, int& dst, int& rel) {
    long long s, d, r;
    if (g_idx64) {
        s = ((const long long*)ei)[w];
        d = ((const long long*)ei)[EE + w];
        r = ((const long long*)et)[w];
    } else {
        s = ((const int*)ei)[w];
        d = ((const int*)ei)[EE + w];
        r = ((const int*)et)[w];
    }
    if ((unsigned long long)s >= NN || (unsigned long long)d >= NN ||
        (unsigned long long)r >= RR) return false;
    src = (int)s; dst = (int)d; rel = (int)r;
    return true;
}

// Fused prep: dtype detect + bucket-count zero + g_Yroot=bias0 + x->fp16.
__global__ void prep_kernel(const float* __restrict__ x,
                            const float* __restrict__ bias0,
                            const int* __restrict__ ei32) {
    int q = blockIdx.x * 256 + threadIdx.x;
    if (q == 0) {                     // int64 edge dtype iff odd int32 words all zero
        int allzero = 1;
        for (int i = 1; i < 64; i += 2)
            if (ei32[i] != 0) allzero = 0;
        g_idx64 = allzero;
    }
    if (q < NB) g_cnt[q] = 0;
    if (q >= NN * (DD / 4)) return;
    float4 b = *(const float4*)(bias0 + (q & 63) * 4);
    *(float4*)(g_Yroot + (size_t)q * 4) = b;
    float4 xv = *(const float4*)(x + (size_t)q * 4);
    __half h[4];
    h[0] = __float2half_rn(xv.x);
    h[1] = __float2half_rn(xv.y);
    h[2] = __float2half_rn(xv.z);
    h[3] = __float2half_rn(xv.w);
    *(uint2*)(g_A16 + (size_t)q * 4) = *(uint2*)h;
}

__global__ void count_kernel(const void* __restrict__ ei, const void* __restrict__ et) {
    int w = blockIdx.x * 256 + threadIdx.x;
    if (w >= EE) return;
    int src, dst, rel;
    if (!load_edge(ei, et, w, src, dst, rel)) return;
    atomicAdd(&g_cnt[(src >> 7) * RR + rel], 1);
}

// single-block exclusive scan of g_cnt -> g_ofs / g_fill (1024 thr x 4 buckets)
__global__ void scan_kernel() {
    __shared__ int s[1024];
    int t = threadIdx.x;
    int v[4], sum = 0;
#pragma unroll
    for (int i = 0; i < 4; i++) {
        int b = t * 4 + i;
        v[i] = (b < NB) ? g_cnt[b] : 0;
        sum += v[i];
    }
    s[t] = sum;
    __syncthreads();
    for (int off = 1; off < 1024; off <<= 1) {
        int x = (t >= off) ? s[t - off] : 0;
        __syncthreads();
        s[t] += x;
        __syncthreads();
    }
    int excl = s[t] - sum;
#pragma unroll
    for (int i = 0; i < 4; i++) {
        int b = t * 4 + i;
        if (b < NB) { g_ofs[b] = excl; g_fill[b] = excl; }
        excl += v[i];
    }
    if (t == 1023) g_ofs[NB] = excl;
}

__global__ void fill_kernel(const void* __restrict__ ei, const void* __restrict__ et) {
    int w = blockIdx.x * 256 + threadIdx.x;
    if (w >= EE) return;
    int src, dst, rel;
    if (!load_edge(ei, et, w, src, dst, rel)) return;
    int b = (src >> 7) * RR + rel;
    int pos = atomicAdd(&g_fill[b], 1);
    g_elist[pos] = ((uint32_t)(src & 127) << 17) | (uint32_t)dst;
}

// ---------------- conversion / activation ----------------
// Weights rounded to fp16, transposed to [l][g][n][k] (k contiguous).
__global__ void conv_w_kernel(const float* __restrict__ weights, const float* __restrict__ roots) {
    size_t i = (size_t)blockIdx.x * 256 + threadIdx.x;
    if (i >= (size_t)3 * GG * DD * DD) return;
    int k = (int)(i & 255);
    int n = (int)((i >> 8) & 255);
    int lg = (int)(i >> 16);
    int l = lg / GG, g = lg % GG;
    float w = (g < 8) ? weights[(((size_t)(l * 8 + g)) * DD + k) * DD + n]
                      : roots[((size_t)l * DD + k) * DD + n];
    g_W16[i] = __float2half_rn(w);
}

// relu(g_Yroot) -> fp16 A; re-init g_Yroot with NEXT layer's bias.
__global__ void act_split_kernel(const float* __restrict__ bias_next) {
    int q = blockIdx.x * 256 + threadIdx.x;         // over NN*DD/4
    if (q >= NN * (DD / 4)) return;
    float4 r = *(const float4*)(g_Yroot + (size_t)q * 4);
    float4 b = *(const float4*)(bias_next + (q & 63) * 4);
    *(float4*)(g_Yroot + (size_t)q * 4) = b;
    __half h[4];
    h[0] = __float2half_rn(fmaxf(r.x, 0.f));
    h[1] = __float2half_rn(fmaxf(r.y, 0.f));
    h[2] = __float2half_rn(fmaxf(r.z, 0.f));
    h[3] = __float2half_rn(fmaxf(r.w, 0.f));
    *(uint2*)(g_A16 + (size_t)q * 4) = *(uint2*)h;
}

__global__ void act_final_kernel(float* __restrict__ out) {
    int q = blockIdx.x * 256 + threadIdx.x;         // over NN*DD/4
    if (q >= NN * (DD / 4)) return;
    float4 r = *(const float4*)(g_Yroot + (size_t)q * 4);
    float4 o;
    o.x = 1.f / (1.f + expf(-r.x));
    o.y = 1.f / (1.f + expf(-r.y));
    o.z = 1.f / (1.f + expf(-r.z));
    o.w = 1.f / (1.f + expf(-r.w));
    *(float4*)(out + (size_t)q * 4) = o;
}

// ---------------- HMMA GEMM + fused scatter epilogue ----------------
// Pure fp16: C = A16 * W16 (1 MMA per fragment pair).
#define BM 128
#define BN 128
#define BK 32
#define STAGES 4
#define LDS_B 64
#define ARR (128 * LDS_B)                  // 8192 bytes per 128x32 fp16 array
#define OFF_A16 0
#define OFF_B16 ARR
#define STAGE_BYTES (2 * ARR)              // 16384
#define CS_STRIDE 132                      // fp32 C staging row stride (padded)
#define SMEM_TOTAL (128 * CS_STRIDE * 4)   // 67584 >= STAGES*STAGE_BYTES (65536)

#define CP_ASYNC16(dst, src, srcsz) \
    asm volatile("cp.async.cg.shared.global [%0], [%1], 16, %2;" \
                 :: "r"(dst), "l"(src), "r"(srcsz) : "memory")
#define CP_COMMIT() asm volatile("cp.async.commit_group;" ::: "memory")
#define CP_WAIT2()  asm volatile("cp.async.wait_group 2;" ::: "memory")

#define LDMX4(r, a) \
    asm volatile("ldmatrix.sync.aligned.m8n8.x4.shared.b16 {%0,%1,%2,%3}, [%4];" \
        : "=r"((r)[0]), "=r"((r)[1]), "=r"((r)[2]), "=r"((r)[3]) : "r"(a))

__device__ __forceinline__ uint32_t smem_u32(const void* p) {
    uint32_t a;
    asm("{ .reg .u64 t; cvta.to.shared.u64 t, %1; cvt.u32.u64 %0, t; }" : "=r"(a) : "l"(p));
    return a;
}
__device__ __forceinline__ uint32_t swz(uint32_t row, uint32_t j) {
    return row * LDS_B + ((j ^ ((row >> 1) & 3u)) << 4);
}
__device__ __forceinline__ void mma16816(float* d, const uint32_t* a, const uint32_t* b) {
    asm volatile(
        "mma.sync.aligned.m16n8k16.row.col.f32.f16.f16.f32 "
        "{%0,%1,%2,%3}, {%4,%5,%6,%7}, {%8,%9}, {%0,%1,%2,%3};"
        : "+f"(d[0]), "+f"(d[1]), "+f"(d[2]), "+f"(d[3])
        : "r"(a[0]), "r"(a[1]), "r"(a[2]), "r"(a[3]), "r"(b[0]), "r"(b[1]));
}

// Single launch, 18 n-tiles. ALL tiles accumulate atomically into g_Yroot.
__global__ __launch_bounds__(256, 2)
void gemm_kernel(int lay) {
    extern __shared__ char smem[];
    const uint32_t sb = smem_u32(smem);
    const int t = threadIdx.x;
    const int wid = t >> 5, lane = t & 31;
    const int g = lane >> 2, t4 = lane & 3;
    const int m0 = blockIdx.x * BM;
    const int nt = blockIdx.y;
    const int warp_m = wid & 3, warp_n = wid >> 2;   // 4 x 2 warp grid

    const int group = nt >> 1, nh = nt & 1;          // group 0..7 rel, 8 root
    const __half* Bp = g_W16 + ((size_t)(lay * GG + group) * DD + nh * 128) * DD;

    float acc[2][8][4];
#pragma unroll
    for (int mi = 0; mi < 2; mi++)
#pragma unroll
        for (int nj = 0; nj < 8; nj++)
#pragma unroll
            for (int q = 0; q < 4; q++) acc[mi][nj][q] = 0.f;

    const int lr = lane & 7;
    const int l8 = (lane >> 3) & 1;
    const int l16 = (lane >> 4) & 1;

    auto load_stage = [&](int kt, int stage) {
        const int k0 = kt * BK;
        const uint32_t stb = sb + stage * STAGE_BYTES;
#pragma unroll
        for (int i = 0; i < 2; i++) {
            int c = t + i * 256;
            uint32_t row = (uint32_t)(c >> 2);
            uint32_t j = (uint32_t)(c & 3);
            uint32_t doff = swz(row, j);
            int col8 = (int)j * 8;
            int gr = m0 + (int)row;
            uint32_t asz = (gr < NN) ? 16u : 0u;
            int grc = (gr < NN) ? gr : 0;
            CP_ASYNC16(stb + OFF_A16 + doff, g_A16 + (size_t)grc * DD + k0 + col8, asz);
            CP_ASYNC16(stb + OFF_B16 + doff, Bp + (size_t)row * DD + k0 + col8, 16u);
        }
    };

    load_stage(0, 0);
    CP_COMMIT();
    load_stage(1, 1);
    CP_COMMIT();
    load_stage(2, 2);
    CP_COMMIT();

    const int NKT = DD / BK;   // 8  (NOT unrolled: keeps regs capped, no spills)
    for (int kt = 0; kt < NKT; kt++) {
        CP_WAIT2();            // stage kt landed
        __syncthreads();       // protects buffer (kt+3)%4 (computed at kt-1)
        if (kt + 3 < NKT) load_stage(kt + 3, (kt + 3) % STAGES);
        CP_COMMIT();

        const uint32_t stf = sb + (kt % STAGES) * STAGE_BYTES;
#pragma unroll
        for (int h = 0; h < 2; h++) {
            uint32_t af[2][4], bf[4][4];
            {
                uint32_t jA = (uint32_t)(h * 2 + l16);
#pragma unroll
                for (int mi = 0; mi < 2; mi++) {
                    uint32_t arow = (uint32_t)(warp_m * 32 + mi * 16 + l8 * 8 + lr);
                    LDMX4(af[mi], stf + swz(arow, jA) + OFF_A16);
                }
            }
            {
                uint32_t jB = (uint32_t)(h * 2 + l8);
#pragma unroll
                for (int p = 0; p < 4; p++) {
                    uint32_t brow = (uint32_t)(warp_n * 64 + p * 16 + l16 * 8 + lr);
                    LDMX4(bf[p], stf + swz(brow, jB) + OFF_B16);
                }
            }
#pragma unroll
            for (int mi = 0; mi < 2; mi++)
#pragma unroll
                for (int p = 0; p < 4; p++) {
                    mma16816(acc[mi][2 * p],     af[mi], &bf[p][0]);
                    mma16816(acc[mi][2 * p + 1], af[mi], &bf[p][2]);
                }
        }
    }

    // Unified epilogue: stage C tile to smem, then atomic-add rows into g_Yroot.
    __syncthreads();                       // all stage-buffer reads done
    float* cs = (float*)smem;              // [128][CS_STRIDE]
#pragma unroll
    for (int mi = 0; mi < 2; mi++) {
        int r0 = warp_m * 32 + mi * 16 + g;
#pragma unroll
        for (int nj = 0; nj < 8; nj++) {
            int cl = warp_n * 64 + nj * 8 + t4 * 2;
            *(float2*)(cs + r0 * CS_STRIDE + cl) =
                make_float2(acc[mi][nj][0], acc[mi][nj][1]);
            *(float2*)(cs + (r0 + 8) * CS_STRIDE + cl) =
                make_float2(acc[mi][nj][2], acc[mi][nj][3]);
        }
    }
    __syncthreads();

    if (group == 8) {
        // Root: identity scatter (row sl -> node m0+sl).
        for (int sl = wid; sl < BM; sl += 8) {
            int dst = m0 + sl;
            if (dst >= NN) break;
            float4 v = *(const float4*)(cs + sl * CS_STRIDE + lane * 4);
            float* p = g_Yroot + (size_t)dst * DD + nh * 128 + lane * 4;
            asm volatile("red.global.add.v4.f32 [%0], {%1, %2, %3, %4};"
                         :: "l"(p), "f"(v.x), "f"(v.y), "f"(v.z), "f"(v.w) : "memory");
        }
    } else {
        // Relations: walk this (src-block, rel) bucket.
        const int bid = blockIdx.x * RR + group;
        const int beg = g_ofs[bid], end = g_ofs[bid + 1];
        for (int i = beg + wid; i < end; i += 8) {
            uint32_t e = g_elist[i];
            int sl = (int)(e >> 17);
            int dst = (int)(e & 0x1FFFF);
            float4 v = *(const float4*)(cs + sl * CS_STRIDE + lane * 4);
            float* p = g_Yroot + (size_t)dst * DD + nh * 128 + lane * 4;
            asm volatile("red.global.add.v4.f32 [%0], {%1, %2, %3, %4};"
                         :: "l"(p), "f"(v.x), "f"(v.y), "f"(v.z), "f"(v.w) : "memory");
        }
    }
}

// ---------------- launch ----------------
extern "C" void kernel_launch(void* const* d_in, const int* in_sizes, int n_in,
                              void* d_out, int out_size) {
    const float* x       = (const float*)d_in[0];
    const float* weights = (const float*)d_in[1];
    const float* roots   = (const float*)d_in[2];
    const float* biases  = (const float*)d_in[3];
    const void*  ei      = d_in[4];
    const void*  et      = d_in[5];

    cudaFuncSetAttribute(gemm_kernel, cudaFuncAttributeMaxDynamicSharedMemorySize, SMEM_TOTAL);

    prep_kernel<<<(NN * DD / 4 + 255) / 256, 256>>>(x, biases, (const int*)ei);
    conv_w_kernel<<<(3 * GG * DD * DD + 255) / 256, 256>>>(weights, roots);
    count_kernel<<<(EE + 255) / 256, 256>>>(ei, et);
    scan_kernel<<<1, 1024>>>();
    fill_kernel<<<(EE + 255) / 256, 256>>>(ei, et);

    for (int l = 0; l < 3; l++) {
        gemm_kernel<<<dim3(391, 18), 256, SMEM_TOTAL>>>(l);
        if (l < 2)
            act_split_kernel<<<(NN * DD / 4 + 255) / 256, 256>>>(biases + (size_t)(l + 1) * DD);
        else
            act_final_kernel<<<(NN * DD / 4 + 255) / 256, 256>>>((float*)d_out);
    }
}